// round 4
// baseline (speedup 1.0000x reference)
#include <cuda_runtime.h>
#include <cstddef>
#include <cstdint>

#define N_BOX 1024
#define HF 192          // feature H = W
#define CF 64           // feature channels
#define S 32            // crop size
#define PS 34           // padded crop size (zero border for SAME convs)
#define CH 64           // conv channels
#define OUTW 30         // VALID conv output

typedef unsigned long long u64;

// -------- static scratch (no allocation allowed) --------
__device__ float g_buf0[(size_t)N_BOX * PS * PS * CH];  // crop, padded
__device__ float g_buf1[(size_t)N_BOX * PS * PS * CH];  // conv1 out, padded
__device__ float g_buf2[(size_t)N_BOX * S * S * CH];    // conv2 out, unpadded

// -------- packed f32x2 helpers (Blackwell FFMA2; ptxas never emits it) -----
__device__ __forceinline__ void ffma2(u64& d, u64 a, u64 b) {
    asm("fma.rn.f32x2 %0, %1, %2, %0;" : "+l"(d) : "l"(a), "l"(b));
}
__device__ __forceinline__ u64 pack2(float v) {
    u64 r;
    asm("mov.b64 %0, {%1, %1};" : "=l"(r) : "r"(__float_as_uint(v)));
    return r;
}
__device__ __forceinline__ void unpack2(u64 v, float& lo, float& hi) {
    uint32_t a, b;
    asm("mov.b64 {%0, %1}, %2;" : "=r"(a), "=r"(b) : "l"(v));
    lo = __uint_as_float(a);
    hi = __uint_as_float(b);
}

// ============================================================
// Kernel 1: crop_and_resize -> g_buf0 (padded, zero border)
// grid (PS, N_BOX), block 256
// ============================================================
__global__ __launch_bounds__(256) void crop_kernel(
    const float* __restrict__ feat,
    const float* __restrict__ boxes,
    const int*   __restrict__ box_ids)
{
    int n  = blockIdx.y;
    int py = blockIdx.x;
    int t  = threadIdx.x;
    float* out = g_buf0 + ((size_t)(n * PS + py)) * PS * CH;

    if (py == 0 || py == PS - 1) {
        for (int i = t; i < PS * CH; i += 256) out[i] = 0.f;
        return;
    }
    int y = py - 1;
    float y1 = boxes[n * 4 + 0], x1 = boxes[n * 4 + 1];
    float y2 = boxes[n * 4 + 2], x2 = boxes[n * 4 + 3];
    int b = box_ids[n];

    float ty  = (float)y / (float)(S - 1);
    float ys  = (y1 + ty * (y2 - y1)) * (float)(HF - 1);
    float y0f = floorf(ys);
    y0f = fminf(fmaxf(y0f, 0.f), (float)(HF - 1));
    float wy  = ys - y0f;
    int y0i = (int)y0f;
    int y1i = min(y0i + 1, HF - 1);

    const float* frow0 = feat + ((size_t)(b * HF + y0i)) * HF * CF;
    const float* frow1 = feat + ((size_t)(b * HF + y1i)) * HF * CF;

    for (int i = t; i < PS * CH; i += 256) {
        int px = i >> 6;
        int c  = i & 63;
        if (px == 0 || px == PS - 1) { out[i] = 0.f; continue; }
        int x = px - 1;
        float tx  = (float)x / (float)(S - 1);
        float xs  = (x1 + tx * (x2 - x1)) * (float)(HF - 1);
        float x0f = floorf(xs);
        x0f = fminf(fmaxf(x0f, 0.f), (float)(HF - 1));
        float wx  = xs - x0f;
        int x0i = (int)x0f;
        int x1i = min(x0i + 1, HF - 1);

        float v00 = frow0[x0i * CF + c];
        float v01 = frow0[x1i * CF + c];
        float v10 = frow1[x0i * CF + c];
        float v11 = frow1[x1i * CF + c];
        float top = v00 * (1.f - wx) + v01 * wx;
        float bot = v10 * (1.f - wx) + v11 * wx;
        out[i] = top * (1.f - wy) + bot * wy;
    }
}

// ============================================================
// Kernel 2: zero the border of g_buf1 (conv1 writes interior only)
// ============================================================
__global__ __launch_bounds__(256) void zero_border_kernel(float* __restrict__ buf)
{
    int n = blockIdx.x;
    int t = threadIdx.x;
    const int TOT = (2 * PS + 2 * S) * CH;
    for (int i = t; i < TOT; i += 256) {
        int c = i & 63;
        int j = i >> 6;
        int py, px;
        if (j < PS)               { py = 0;                  px = j; }
        else if (j < 2 * PS)      { py = PS - 1;             px = j - PS; }
        else if (j < 2 * PS + S)  { py = j - 2 * PS + 1;     px = 0; }
        else                      { py = j - (2 * PS + S) + 1; px = PS - 1; }
        buf[((size_t)(n * PS + py) * PS + px) * CH + c] = 0.f;
    }
}

// ============================================================
// Kernel 3/4: 3x3 conv (64->64) + bias + ReLU, packed f32x2 over co-pairs.
// grid (8 row-tiles, N_BOX), block 256 = 32 x-cols * 8 co-groups (8 co each).
// ci chunked 4x16.  smem: wsm[9][16][64] f32 + slab2[16][6][34] u64 ({v,v})
// ============================================================
#define CI_CHUNK 16
#define WSM_FLOATS (9 * CI_CHUNK * 64)                 // 9216
#define SLAB2_U64  (CI_CHUNK * 6 * 34)                 // 3264
#define CONV_SMEM_BYTES (WSM_FLOATS * 4 + SLAB2_U64 * 8)  // 62976

template <bool PAD_OUT>
__global__ __launch_bounds__(256, 3) void conv3x3_kernel(
    const float* __restrict__ in,    // padded input [N][34][34][64]
    float*       __restrict__ outbuf,
    const float* __restrict__ w,     // [3][3][64][64]
    const float* __restrict__ bias)
{
    extern __shared__ char smraw[];
    float* wsm  = (float*)smraw;                        // [9][16][64]
    u64*   slab = (u64*)(smraw + WSM_FLOATS * 4);       // [16][6][34] packed {v,v}

    int n    = blockIdx.y;
    int tile = blockIdx.x;           // output rows tile*4 .. tile*4+3
    int t    = threadIdx.x;
    int x    = t & 31;
    int g    = t >> 5;               // co group, co = g*8..g*8+7

    u64 acc2[4][4];
#pragma unroll
    for (int r = 0; r < 4; r++)
#pragma unroll
        for (int j = 0; j < 4; j++) acc2[r][j] = 0ull;

    const float4* in4 = (const float4*)in;
    const float4* w4g = (const float4*)w;

    for (int cb = 0; cb < 4; cb++) {
        // ---- input slab: rows tile*4..tile*4+5, 34 px, 16 ci, duplicated {v,v}
        for (int idx = t; idx < 6 * 34 * 4; idx += 256) {
            int ci4 = idx & 3;
            int rem = idx >> 2;
            int px  = rem % 34;
            int row = rem / 34;
            float4 v = in4[((size_t)(n * PS + tile * 4 + row) * PS + px) * (CH / 4)
                           + cb * 4 + ci4];
            int cibase = ci4 * 4;
            slab[(cibase + 0) * 204 + row * 34 + px] = pack2(v.x);
            slab[(cibase + 1) * 204 + row * 34 + px] = pack2(v.y);
            slab[(cibase + 2) * 204 + row * 34 + px] = pack2(v.z);
            slab[(cibase + 3) * 204 + row * 34 + px] = pack2(v.w);
        }
        // ---- weight chunk [9][16][64]
        for (int idx = t; idx < 9 * CI_CHUNK * 16; idx += 256) {
            int co4 = idx & 15;
            int rem = idx >> 4;
            int ci  = rem & 15;
            int p   = rem >> 4;
            ((float4*)wsm)[(p * CI_CHUNK + ci) * 16 + co4] =
                w4g[((size_t)(p * 64 + cb * CI_CHUNK + ci)) * 16 + co4];
        }
        __syncthreads();

#pragma unroll
        for (int p = 0; p < 9; p++) {
            const int ky = p / 3, kx = p % 3;
            const u64* srow = slab + ky * 34 + x + kx;
            // wsm float index (p*16+ci)*64 + g*8  ->  ulonglong2 index /4
            const ulonglong2* wrow =
                (const ulonglong2*)wsm + (size_t)p * CI_CHUNK * 16 + g * 2;
#pragma unroll 4
            for (int ci = 0; ci < CI_CHUNK; ci++) {
                ulonglong2 wab = wrow[ci * 16];       // co pairs {0,1},{2,3}
                ulonglong2 wcd = wrow[ci * 16 + 1];   // co pairs {4,5},{6,7}
                const u64* sp = srow + ci * 204;
#pragma unroll
                for (int r = 0; r < 4; r++) {
                    u64 ss = sp[r * 34];
                    ffma2(acc2[r][0], ss, wab.x);
                    ffma2(acc2[r][1], ss, wab.y);
                    ffma2(acc2[r][2], ss, wcd.x);
                    ffma2(acc2[r][3], ss, wcd.y);
                }
            }
        }
        __syncthreads();
    }

    int co0 = g * 8;
    float bv[8];
#pragma unroll
    for (int o = 0; o < 8; o++) bv[o] = __ldg(&bias[co0 + o]);

#pragma unroll
    for (int r = 0; r < 4; r++) {
        int y = tile * 4 + r;
        float* op;
        if (PAD_OUT)
            op = outbuf + (((size_t)(n * PS + y + 1) * PS) + x + 1) * CH + co0;
        else
            op = outbuf + (((size_t)(n * S + y) * S) + x) * CH + co0;
        float a[8];
#pragma unroll
        for (int j = 0; j < 4; j++) unpack2(acc2[r][j], a[2 * j], a[2 * j + 1]);
        float4 o0, o1;
        o0.x = fmaxf(a[0] + bv[0], 0.f);
        o0.y = fmaxf(a[1] + bv[1], 0.f);
        o0.z = fmaxf(a[2] + bv[2], 0.f);
        o0.w = fmaxf(a[3] + bv[3], 0.f);
        o1.x = fmaxf(a[4] + bv[4], 0.f);
        o1.y = fmaxf(a[5] + bv[5], 0.f);
        o1.z = fmaxf(a[6] + bv[6], 0.f);
        o1.w = fmaxf(a[7] + bv[7], 0.f);
        ((float4*)op)[0] = o0;
        ((float4*)op)[1] = o1;
    }
}

// ============================================================
// Kernel 5: 3x3 VALID conv, ONLY the selected class channel
// ============================================================
__global__ __launch_bounds__(256) void outconv_kernel(
    const float* __restrict__ buf2,  // [N][32][32][64]
    const float* __restrict__ ow,    // [3][3][64][3]
    const float* __restrict__ ob,    // [3]
    const int*   __restrict__ cls,
    float*       __restrict__ out)   // [N][30][30]
{
    __shared__ float ws[576];            // [9][64] weight slice for this class
    __shared__ float insm[64 * 3 * 32];  // [ci][ry][x]
    __shared__ float red[8][32];

    int n = blockIdx.x;
    int t = threadIdx.x;
    int k = __ldg(&cls[n]);

    for (int i = t; i < 576; i += 256) ws[i] = ow[i * 3 + k];
    float bias = __ldg(&ob[k]);

    int ox  = t & 31;
    int grp = t >> 5;
    const float4* b2 = (const float4*)buf2;

    for (int oy = 0; oy < OUTW; oy++) {
        __syncthreads();
        for (int idx = t; idx < 3 * 32 * 16; idx += 256) {
            int ci4 = idx & 15;
            int rem = idx >> 4;
            int px  = rem & 31;
            int ry  = rem >> 5;
            float4 v = b2[((size_t)(n * S + oy + ry) * S + px) * 16 + ci4];
            int cb = ci4 * 4;
            insm[(cb + 0) * 96 + ry * 32 + px] = v.x;
            insm[(cb + 1) * 96 + ry * 32 + px] = v.y;
            insm[(cb + 2) * 96 + ry * 32 + px] = v.z;
            insm[(cb + 3) * 96 + ry * 32 + px] = v.w;
        }
        __syncthreads();

        float part = 0.f;
        if (ox < OUTW) {
#pragma unroll
            for (int p = 0; p < 9; p++) {
                const int ky = p / 3, kx = p % 3;
#pragma unroll
                for (int ci = 0; ci < 8; ci++) {
                    int cig = grp * 8 + ci;
                    part += insm[cig * 96 + ky * 32 + ox + kx] * ws[p * 64 + cig];
                }
            }
        }
        red[grp][ox] = part;
        __syncthreads();
        if (grp == 0 && ox < OUTW) {
            float ssum = bias;
#pragma unroll
            for (int q = 0; q < 8; q++) ssum += red[q][ox];
            out[(size_t)n * (OUTW * OUTW) + oy * OUTW + ox] = ssum;
        }
    }
}

// ============================================================
// Launch
// ============================================================
extern "C" void kernel_launch(void* const* d_in, const int* in_sizes, int n_in,
                              void* d_out, int out_size)
{
    const float* features = (const float*)d_in[0];
    const float* boxes    = (const float*)d_in[1];
    const int*   box_ids  = (const int*)d_in[2];
    const int*   cls      = (const int*)d_in[3];
    const float* w1       = (const float*)d_in[4];
    const float* b1       = (const float*)d_in[5];
    const float* w2       = (const float*)d_in[6];
    const float* b2       = (const float*)d_in[7];
    const float* ow       = (const float*)d_in[8];
    const float* ob       = (const float*)d_in[9];
    float* out = (float*)d_out;

    cudaFuncSetAttribute(conv3x3_kernel<true>,
                         cudaFuncAttributeMaxDynamicSharedMemorySize, CONV_SMEM_BYTES);
    cudaFuncSetAttribute(conv3x3_kernel<false>,
                         cudaFuncAttributeMaxDynamicSharedMemorySize, CONV_SMEM_BYTES);

    void *p0 = nullptr, *p1 = nullptr, *p2 = nullptr;
    cudaGetSymbolAddress(&p0, g_buf0);
    cudaGetSymbolAddress(&p1, g_buf1);
    cudaGetSymbolAddress(&p2, g_buf2);

    crop_kernel<<<dim3(PS, N_BOX), 256>>>(features, boxes, box_ids);
    zero_border_kernel<<<N_BOX, 256>>>((float*)p1);
    conv3x3_kernel<true><<<dim3(8, N_BOX), 256, CONV_SMEM_BYTES>>>(
        (const float*)p0, (float*)p1, w1, b1);
    conv3x3_kernel<false><<<dim3(8, N_BOX), 256, CONV_SMEM_BYTES>>>(
        (const float*)p1, (float*)p2, w2, b2);
    outconv_kernel<<<N_BOX, 256>>>((const float*)p2, ow, ob, cls, out);
}

// round 6
// speedup vs baseline: 1.8283x; 1.8283x over previous
#include <cuda_runtime.h>
#include <cuda_bf16.h>
#include <cstddef>
#include <cstdint>

typedef unsigned long long u64;
typedef unsigned int u32;

#define N_BOX 1024
#define HF 192
#define CF 64
#define S 32
#define CH 64
#define OUTW 30

// =================== static scratch ===================
// slabs: [box][34 rows][32 px][64 ch] bf16 ; rows 0,33 zero guards; row j = image row j-1
__device__ __nv_bfloat16 g_s1_hi[(size_t)N_BOX * 34 * 32 * 64];
__device__ __nv_bfloat16 g_s1_lo[(size_t)N_BOX * 34 * 32 * 64];
__device__ __nv_bfloat16 g_s2_hi[(size_t)N_BOX * 34 * 32 * 64];
__device__ __nv_bfloat16 g_s2_lo[(size_t)N_BOX * 34 * 32 * 64];
__device__ float g_buf2[(size_t)N_BOX * S * S * CH];   // conv2 out fp32
// B fragments in mma.sync register order:
// [layer][tap][split][kstep][ntile][lane] x {b0,b1} u32
__device__ u32 g_wfrag[2 * 9 * 2 * 4 * 8 * 32 * 2];

__device__ __forceinline__ u32 pbf2(float a, float b) {
    __nv_bfloat162 t = __floats2bfloat162_rn(a, b);
    return *(u32*)&t;
}
__device__ __forceinline__ float bfhi(float v) {
    return __bfloat162float(__float2bfloat16(v));
}
__device__ __forceinline__ void mma16816(float* c, const u32* a, u32 b0, u32 b1) {
    asm volatile(
        "mma.sync.aligned.m16n8k16.row.col.f32.bf16.bf16.f32 "
        "{%0,%1,%2,%3}, {%4,%5,%6,%7}, {%8,%9}, {%0,%1,%2,%3};"
        : "+f"(c[0]), "+f"(c[1]), "+f"(c[2]), "+f"(c[3])
        : "r"(a[0]), "r"(a[1]), "r"(a[2]), "r"(a[3]), "r"(b0), "r"(b1));
}

// ============================================================
// Kernel 1: crop_and_resize -> g_s1_hi/lo (guard rows 0/33)
// ============================================================
__global__ __launch_bounds__(256) void crop_kernel(
    const float* __restrict__ feat,
    const float* __restrict__ boxes,
    const int*   __restrict__ box_ids)
{
    int n  = blockIdx.y;
    int py = blockIdx.x;
    int t  = threadIdx.x;
    size_t rb = ((size_t)n * 34 + py) * 32 * 64;

    if (py == 0 || py == 33) {
        __nv_bfloat16 z = __float2bfloat16(0.f);
        for (int i = t; i < 32 * 64; i += 256) { g_s1_hi[rb + i] = z; g_s1_lo[rb + i] = z; }
        return;
    }
    int y = py - 1;
    float y1 = boxes[n * 4 + 0], x1 = boxes[n * 4 + 1];
    float y2 = boxes[n * 4 + 2], x2 = boxes[n * 4 + 3];
    int b = box_ids[n];

    float ty  = (float)y / (float)(S - 1);
    float ys  = (y1 + ty * (y2 - y1)) * (float)(HF - 1);
    float y0f = fminf(fmaxf(floorf(ys), 0.f), (float)(HF - 1));
    float wy  = ys - y0f;
    int y0i = (int)y0f;
    int y1i = min(y0i + 1, HF - 1);

    const float* frow0 = feat + ((size_t)(b * HF + y0i)) * HF * CF;
    const float* frow1 = feat + ((size_t)(b * HF + y1i)) * HF * CF;

    for (int i = t; i < 32 * 64; i += 256) {
        int x = i >> 6;
        int c = i & 63;
        float tx  = (float)x / (float)(S - 1);
        float xs  = (x1 + tx * (x2 - x1)) * (float)(HF - 1);
        float x0f = fminf(fmaxf(floorf(xs), 0.f), (float)(HF - 1));
        float wx  = xs - x0f;
        int x0i = (int)x0f;
        int x1i = min(x0i + 1, HF - 1);

        float v00 = frow0[x0i * CF + c];
        float v01 = frow0[x1i * CF + c];
        float v10 = frow1[x0i * CF + c];
        float v11 = frow1[x1i * CF + c];
        float top = v00 * (1.f - wx) + v01 * wx;
        float bot = v10 * (1.f - wx) + v11 * wx;
        float v   = top * (1.f - wy) + bot * wy;
        float h = bfhi(v);
        g_s1_hi[rb + i] = __float2bfloat16(h);
        g_s1_lo[rb + i] = __float2bfloat16(v - h);
    }
}

// ============================================================
// Kernel 2: zero guard rows (0, 33) of s2 slabs
// ============================================================
__global__ __launch_bounds__(256) void zero_s2_guards()
{
    int n = blockIdx.x;
    int t = threadIdx.x;
    size_t r0 = ((size_t)n * 34 + 0) * 2048;
    size_t r1 = ((size_t)n * 34 + 33) * 2048;
    __nv_bfloat16 z = __float2bfloat16(0.f);
    for (int i = t; i < 2048; i += 256) {
        g_s2_hi[r0 + i] = z; g_s2_hi[r1 + i] = z;
        g_s2_lo[r0 + i] = z; g_s2_lo[r1 + i] = z;
    }
}

// ============================================================
// Kernel 3: weight prep -> mma B-fragment order, hi/lo split
// ============================================================
__global__ __launch_bounds__(256) void wprep_kernel(
    const float* __restrict__ w1, const float* __restrict__ w2)
{
    int i = blockIdx.x * 256 + threadIdx.x;
    if (i >= 36864) return;
    int layer = i / 18432;
    int r     = i % 18432;
    int tap   = r / 2048;
    int r2    = r & 2047;
    int split = r2 >> 10;
    int ks    = (r2 >> 8) & 3;
    int nt    = (r2 >> 5) & 7;
    int lane  = r2 & 31;
    int gid = lane >> 2, ctg = lane & 3;
    int ci0 = ks * 16 + ctg * 2;
    int co  = nt * 8 + gid;
    const float* W = layer ? w2 : w1;

    float v, h, s0, s1, s2, s3;
    v = W[(tap * 64 + ci0) * 64 + co];     h = bfhi(v); s0 = split ? (v - h) : h;
    v = W[(tap * 64 + ci0 + 1) * 64 + co]; h = bfhi(v); s1 = split ? (v - h) : h;
    v = W[(tap * 64 + ci0 + 8) * 64 + co]; h = bfhi(v); s2 = split ? (v - h) : h;
    v = W[(tap * 64 + ci0 + 9) * 64 + co]; h = bfhi(v); s3 = split ? (v - h) : h;

    g_wfrag[i * 2]     = pbf2(s0, s1);
    g_wfrag[i * 2 + 1] = pbf2(s2, s3);
}

// ============================================================
// Kernel 4/5: HMMA conv 3x3 (64->64) + bias + ReLU
// CTA = one box, 256 threads (8 warps). Outer loop: 8 m-blocks of 4 rows.
// Warp tile: M=16 (m16 tile wid), N=64 (8 n8 tiles), 3 bf16 passes.
// smem: ws frags 147456 B + slab_hi 26112 + slab_lo 26112 + bias 256
// ============================================================
#define WS_U32     36864
#define OFF_SHI    147456
#define OFF_SLO    173568
#define OFF_BIAS   199680
#define CONV_SMEM_BYTES (199680 + 256)

template <int MODE>
__global__ __launch_bounds__(256, 1) void conv_mma_kernel(
    const __nv_bfloat16* __restrict__ in_hi,
    const __nv_bfloat16* __restrict__ in_lo,
    const u32* __restrict__ wfrag,   // this layer's fragment array
    const float* __restrict__ bias)
{
    extern __shared__ char smraw[];
    u32*   ws      = (u32*)smraw;                    // fragment array
    u32*   slab_hi = (u32*)(smraw + OFF_SHI);        // [6][34][32 words] swizzled
    u32*   slab_lo = (u32*)(smraw + OFF_SLO);
    float* bias_s  = (float*)(smraw + OFF_BIAS);

    int n   = blockIdx.x;
    int t   = threadIdx.x;
    int wid = t >> 5;
    int lane = t & 31;
    int gid = lane >> 2, ctg = lane & 3;

    // one-time loads
    {
        const uint4* wsrc = (const uint4*)wfrag;
        uint4* wdst = (uint4*)ws;
        for (int i = t; i < WS_U32 / 4; i += 256) wdst[i] = wsrc[i];
        if (t < 64) bias_s[t] = bias[t];
    }

    int m_lo = wid * 16 + gid;        // rows of C frags
    int m_hi = m_lo + 8;
    int row_lo = m_lo >> 5, x_lo = m_lo & 31;
    int row_hi = m_hi >> 5, x_hi = m_hi & 31;

#pragma unroll 1
    for (int it = 0; it < 8; it++) {
        __syncthreads();   // previous iteration fully consumed smem (also covers ws load)
        // ---- load slab rows 4it .. 4it+5 (hi and lo), x-guarded + swizzled
#pragma unroll 1
        for (int s = 0; s < 2; s++) {
            const uint4* src = (const uint4*)(s ? in_lo : in_hi);
            u32* dst = s ? slab_lo : slab_hi;
            for (int idx = t; idx < 1536; idx += 256) {
                int c  = idx & 7;
                int px = (idx >> 3) & 31;
                int r  = idx >> 8;
                uint4 v = src[((size_t)(n * 34 + it * 4 + r) * 32 + px) * 8 + c];
                int sw = ((px + 1) & 7) << 2;
                int w  = (r * 34 + px + 1) * 32 + ((c * 4) ^ sw);
                *(uint4*)(dst + w) = v;
            }
            for (int idx = t; idx < 96; idx += 256) {   // zero guards px_s = 0, 33
                int c = idx & 7;
                int side = (idx >> 3) & 1;
                int r = idx >> 4;
                int pxs = side ? 33 : 0;
                int sw = (pxs & 7) << 2;
                int w = (r * 34 + pxs) * 32 + ((c * 4) ^ sw);
                *(uint4*)(dst + w) = make_uint4(0, 0, 0, 0);
            }
        }
        __syncthreads();

        float acc[8][4];
#pragma unroll
        for (int nt = 0; nt < 8; nt++)
#pragma unroll
            for (int j = 0; j < 4; j++) acc[nt][j] = 0.f;

#pragma unroll 1
        for (int tap = 0; tap < 9; tap++) {
            int ky = tap / 3, kx = tap - ky * 3;
            int rl = row_lo + ky, pl = x_lo + kx;
            int rh = row_hi + ky, ph = x_hi + kx;
            int bl_ = (rl * 34 + pl) * 32, sl_ = (pl & 7) << 2;
            int bh_ = (rh * 34 + ph) * 32, sh_ = (ph & 7) << 2;
#pragma unroll
            for (int ks = 0; ks < 4; ks++) {
                int c0 = ks * 8 + ctg, c1 = ks * 8 + 4 + ctg;
                u32 ah[4], al[4];
                ah[0] = slab_hi[bl_ + (c0 ^ sl_)];
                ah[1] = slab_hi[bh_ + (c0 ^ sh_)];
                ah[2] = slab_hi[bl_ + (c1 ^ sl_)];
                ah[3] = slab_hi[bh_ + (c1 ^ sh_)];
                al[0] = slab_lo[bl_ + (c0 ^ sl_)];
                al[1] = slab_lo[bh_ + (c0 ^ sh_)];
                al[2] = slab_lo[bl_ + (c1 ^ sl_)];
                al[3] = slab_lo[bh_ + (c1 ^ sh_)];

                const uint2* wh = (const uint2*)ws + (((tap * 2 + 0) * 4 + ks) * 8) * 32;
                const uint2* wl = (const uint2*)ws + (((tap * 2 + 1) * 4 + ks) * 8) * 32;
#pragma unroll
                for (int nt = 0; nt < 8; nt++) {
                    uint2 bh2 = wh[nt * 32 + lane];
                    mma16816(acc[nt], ah, bh2.x, bh2.y);
                    mma16816(acc[nt], al, bh2.x, bh2.y);
                    uint2 bl2 = wl[nt * 32 + lane];
                    mma16816(acc[nt], ah, bl2.x, bl2.y);
                }
            }
        }

        // ---- epilogue: bias + ReLU, write
        int y0 = it * 4 + row_lo;
        int y1 = it * 4 + row_hi;
#pragma unroll
        for (int nt = 0; nt < 8; nt++) {
            int co = nt * 8 + ctg * 2;
            float v00 = fmaxf(acc[nt][0] + bias_s[co], 0.f);
            float v01 = fmaxf(acc[nt][1] + bias_s[co + 1], 0.f);
            float v10 = fmaxf(acc[nt][2] + bias_s[co], 0.f);
            float v11 = fmaxf(acc[nt][3] + bias_s[co + 1], 0.f);
            if (MODE == 0) {
                size_t a0 = (((size_t)n * 34 + y0 + 1) * 32 + x_lo) * 64 + co;
                size_t a1 = (((size_t)n * 34 + y1 + 1) * 32 + x_hi) * 64 + co;
                float h00 = bfhi(v00), h01 = bfhi(v01);
                float h10 = bfhi(v10), h11 = bfhi(v11);
                *(u32*)&g_s2_hi[a0] = pbf2(h00, h01);
                *(u32*)&g_s2_lo[a0] = pbf2(v00 - h00, v01 - h01);
                *(u32*)&g_s2_hi[a1] = pbf2(h10, h11);
                *(u32*)&g_s2_lo[a1] = pbf2(v10 - h10, v11 - h11);
            } else {
                size_t a0 = (((size_t)n * 32 + y0) * 32 + x_lo) * 64 + co;
                size_t a1 = (((size_t)n * 32 + y1) * 32 + x_hi) * 64 + co;
                *(float2*)&g_buf2[a0] = make_float2(v00, v01);
                *(float2*)&g_buf2[a1] = make_float2(v10, v11);
            }
        }
    }
}

// ============================================================
// Kernel 6: 3x3 VALID conv, only the selected class channel
// ============================================================
__global__ __launch_bounds__(256) void outconv_kernel(
    const float* __restrict__ buf2,
    const float* __restrict__ ow,    // [3][3][64][3]
    const float* __restrict__ ob,
    const int*   __restrict__ cls,
    float*       __restrict__ out)   // [N][30][30]
{
    __shared__ float ws[576];
    __shared__ float insm[64 * 3 * 32];
    __shared__ float red[8][32];

    int n = blockIdx.x;
    int t = threadIdx.x;
    int k = __ldg(&cls[n]);

    for (int i = t; i < 576; i += 256) ws[i] = ow[i * 3 + k];
    float bias = __ldg(&ob[k]);

    int ox  = t & 31;
    int grp = t >> 5;
    const float4* b2 = (const float4*)buf2;

    for (int oy = 0; oy < OUTW; oy++) {
        __syncthreads();
        for (int idx = t; idx < 3 * 32 * 16; idx += 256) {
            int ci4 = idx & 15;
            int rem = idx >> 4;
            int px  = rem & 31;
            int ry  = rem >> 5;
            float4 v = b2[((size_t)(n * S + oy + ry) * S + px) * 16 + ci4];
            int cb = ci4 * 4;
            insm[(cb + 0) * 96 + ry * 32 + px] = v.x;
            insm[(cb + 1) * 96 + ry * 32 + px] = v.y;
            insm[(cb + 2) * 96 + ry * 32 + px] = v.z;
            insm[(cb + 3) * 96 + ry * 32 + px] = v.w;
        }
        __syncthreads();

        float part = 0.f;
        if (ox < OUTW) {
#pragma unroll
            for (int p = 0; p < 9; p++) {
                const int ky = p / 3, kx = p % 3;
#pragma unroll
                for (int ci = 0; ci < 8; ci++) {
                    int cig = grp * 8 + ci;
                    part += insm[cig * 96 + ky * 32 + ox + kx] * ws[p * 64 + cig];
                }
            }
        }
        red[grp][ox] = part;
        __syncthreads();
        if (grp == 0 && ox < OUTW) {
            float ssum = bias;
#pragma unroll
            for (int q = 0; q < 8; q++) ssum += red[q][ox];
            out[(size_t)n * (OUTW * OUTW) + oy * OUTW + ox] = ssum;
        }
    }
}

// ============================================================
// Launch
// ============================================================
extern "C" void kernel_launch(void* const* d_in, const int* in_sizes, int n_in,
                              void* d_out, int out_size)
{
    const float* features = (const float*)d_in[0];
    const float* boxes    = (const float*)d_in[1];
    const int*   box_ids  = (const int*)d_in[2];
    const int*   cls      = (const int*)d_in[3];
    const float* w1       = (const float*)d_in[4];
    const float* b1       = (const float*)d_in[5];
    const float* w2       = (const float*)d_in[6];
    const float* b2       = (const float*)d_in[7];
    const float* ow       = (const float*)d_in[8];
    const float* ob       = (const float*)d_in[9];
    float* out = (float*)d_out;

    cudaFuncSetAttribute(conv_mma_kernel<0>,
                         cudaFuncAttributeMaxDynamicSharedMemorySize, CONV_SMEM_BYTES);
    cudaFuncSetAttribute(conv_mma_kernel<1>,
                         cudaFuncAttributeMaxDynamicSharedMemorySize, CONV_SMEM_BYTES);

    void *s1h, *s1l, *s2h, *s2l, *wf, *p2;
    cudaGetSymbolAddress(&s1h, g_s1_hi);
    cudaGetSymbolAddress(&s1l, g_s1_lo);
    cudaGetSymbolAddress(&s2h, g_s2_hi);
    cudaGetSymbolAddress(&s2l, g_s2_lo);
    cudaGetSymbolAddress(&wf,  g_wfrag);
    cudaGetSymbolAddress(&p2,  g_buf2);

    crop_kernel<<<dim3(34, N_BOX), 256>>>(features, boxes, box_ids);
    zero_s2_guards<<<N_BOX, 256>>>();
    wprep_kernel<<<144, 256>>>(w1, w2);

    conv_mma_kernel<0><<<N_BOX, 256, CONV_SMEM_BYTES>>>(
        (const __nv_bfloat16*)s1h, (const __nv_bfloat16*)s1l,
        (const u32*)wf, b1);
    conv_mma_kernel<1><<<N_BOX, 256, CONV_SMEM_BYTES>>>(
        (const __nv_bfloat16*)s2h, (const __nv_bfloat16*)s2l,
        (const u32*)wf + 36864, b2);

    outconv_kernel<<<N_BOX, 256>>>((const float*)p2, ow, ob, cls, out);
}

// round 8
// speedup vs baseline: 2.3844x; 1.3042x over previous
#include <cuda_runtime.h>
#include <cuda_bf16.h>
#include <cstddef>
#include <cstdint>

typedef unsigned long long u64;
typedef unsigned int u32;

#define N_BOX 1024
#define HF 192
#define CF 64
#define S 32
#define CH 64
#define OUTW 30

// =================== static scratch ===================
// slabs: [box][34 rows][32 px][64 ch] bf16 ; rows 0,33 zero guards; row j = image row j-1
__device__ __nv_bfloat16 g_s1_hi[(size_t)N_BOX * 34 * 32 * 64];
__device__ __nv_bfloat16 g_s1_lo[(size_t)N_BOX * 34 * 32 * 64];
__device__ __nv_bfloat16 g_s2_hi[(size_t)N_BOX * 34 * 32 * 64];
__device__ __nv_bfloat16 g_s2_lo[(size_t)N_BOX * 34 * 32 * 64];
__device__ float g_buf2[(size_t)N_BOX * S * S * CH];   // conv2 out fp32
// B fragments in mma.sync register order:
// [layer][tap][split][kstep][ntile][lane] x {b0,b1} u32
__device__ u32 g_wfrag[2 * 9 * 2 * 4 * 8 * 32 * 2];

__device__ __forceinline__ u32 pbf2(float a, float b) {
    __nv_bfloat162 t = __floats2bfloat162_rn(a, b);
    return *(u32*)&t;
}
__device__ __forceinline__ float bfhi(float v) {
    return __bfloat162float(__float2bfloat16(v));
}
__device__ __forceinline__ void mma16816(float* c, const u32* a, u32 b0, u32 b1) {
    asm volatile(
        "mma.sync.aligned.m16n8k16.row.col.f32.bf16.bf16.f32 "
        "{%0,%1,%2,%3}, {%4,%5,%6,%7}, {%8,%9}, {%0,%1,%2,%3};"
        : "+f"(c[0]), "+f"(c[1]), "+f"(c[2]), "+f"(c[3])
        : "r"(a[0]), "r"(a[1]), "r"(a[2]), "r"(a[3]), "r"(b0), "r"(b1));
}

// ============================================================
// Kernel 1: crop_and_resize -> g_s1_hi/lo (guard rows 0/33)
// ============================================================
__global__ __launch_bounds__(256) void crop_kernel(
    const float* __restrict__ feat,
    const float* __restrict__ boxes,
    const int*   __restrict__ box_ids)
{
    int n  = blockIdx.y;
    int py = blockIdx.x;
    int t  = threadIdx.x;
    size_t rb = ((size_t)n * 34 + py) * 32 * 64;

    if (py == 0 || py == 33) {
        __nv_bfloat16 z = __float2bfloat16(0.f);
        for (int i = t; i < 32 * 64; i += 256) { g_s1_hi[rb + i] = z; g_s1_lo[rb + i] = z; }
        return;
    }
    int y = py - 1;
    float y1 = boxes[n * 4 + 0], x1 = boxes[n * 4 + 1];
    float y2 = boxes[n * 4 + 2], x2 = boxes[n * 4 + 3];
    int b = box_ids[n];

    float ty  = (float)y / (float)(S - 1);
    float ys  = (y1 + ty * (y2 - y1)) * (float)(HF - 1);
    float y0f = fminf(fmaxf(floorf(ys), 0.f), (float)(HF - 1));
    float wy  = ys - y0f;
    int y0i = (int)y0f;
    int y1i = min(y0i + 1, HF - 1);

    const float* frow0 = feat + ((size_t)(b * HF + y0i)) * HF * CF;
    const float* frow1 = feat + ((size_t)(b * HF + y1i)) * HF * CF;

    for (int i = t; i < 32 * 64; i += 256) {
        int x = i >> 6;
        int c = i & 63;
        float tx  = (float)x / (float)(S - 1);
        float xs  = (x1 + tx * (x2 - x1)) * (float)(HF - 1);
        float x0f = fminf(fmaxf(floorf(xs), 0.f), (float)(HF - 1));
        float wx  = xs - x0f;
        int x0i = (int)x0f;
        int x1i = min(x0i + 1, HF - 1);

        float v00 = frow0[x0i * CF + c];
        float v01 = frow0[x1i * CF + c];
        float v10 = frow1[x0i * CF + c];
        float v11 = frow1[x1i * CF + c];
        float top = v00 * (1.f - wx) + v01 * wx;
        float bot = v10 * (1.f - wx) + v11 * wx;
        float v   = top * (1.f - wy) + bot * wy;
        float h = bfhi(v);
        g_s1_hi[rb + i] = __float2bfloat16(h);
        g_s1_lo[rb + i] = __float2bfloat16(v - h);
    }
}

// ============================================================
// Kernel 2: zero guard rows (0, 33) of s2 slabs
// ============================================================
__global__ __launch_bounds__(256) void zero_s2_guards()
{
    int n = blockIdx.x;
    int t = threadIdx.x;
    size_t r0 = ((size_t)n * 34 + 0) * 2048;
    size_t r1 = ((size_t)n * 34 + 33) * 2048;
    __nv_bfloat16 z = __float2bfloat16(0.f);
    for (int i = t; i < 2048; i += 256) {
        g_s2_hi[r0 + i] = z; g_s2_hi[r1 + i] = z;
        g_s2_lo[r0 + i] = z; g_s2_lo[r1 + i] = z;
    }
}

// ============================================================
// Kernel 3: weight prep -> mma B-fragment order, hi/lo split
// ============================================================
__global__ __launch_bounds__(256) void wprep_kernel(
    const float* __restrict__ w1, const float* __restrict__ w2)
{
    int i = blockIdx.x * 256 + threadIdx.x;
    if (i >= 36864) return;
    int layer = i / 18432;
    int r     = i % 18432;
    int tap   = r / 2048;
    int r2    = r & 2047;
    int split = r2 >> 10;
    int ks    = (r2 >> 8) & 3;
    int nt    = (r2 >> 5) & 7;
    int lane  = r2 & 31;
    int gid = lane >> 2, ctg = lane & 3;
    int ci0 = ks * 16 + ctg * 2;
    int co  = nt * 8 + gid;
    const float* W = layer ? w2 : w1;

    float v, h, s0, s1, s2, s3;
    v = W[(tap * 64 + ci0) * 64 + co];     h = bfhi(v); s0 = split ? (v - h) : h;
    v = W[(tap * 64 + ci0 + 1) * 64 + co]; h = bfhi(v); s1 = split ? (v - h) : h;
    v = W[(tap * 64 + ci0 + 8) * 64 + co]; h = bfhi(v); s2 = split ? (v - h) : h;
    v = W[(tap * 64 + ci0 + 9) * 64 + co]; h = bfhi(v); s3 = split ? (v - h) : h;

    g_wfrag[i * 2]     = pbf2(s0, s1);
    g_wfrag[i * 2 + 1] = pbf2(s2, s3);
}

// ============================================================
// Kernel 4/5: HMMA conv 3x3 (64->64) + bias + ReLU
// CTA = one box, 256 threads (8 warps), 2 CTAs/SM.
// B fragments read straight from global (L1/L2 broadcast-resident).
// 3 passes restructured into independent sweeps over nt (no RAW chains).
// smem: slab_hi 26112 + slab_lo 26112 + bias 256
// ============================================================
#define OFF_SLO    26112
#define OFF_BIAS   52224
#define CONV_SMEM_BYTES (52224 + 256)

template <int MODE>
__global__ __launch_bounds__(256, 2) void conv_mma_kernel(
    const __nv_bfloat16* __restrict__ in_hi,
    const __nv_bfloat16* __restrict__ in_lo,
    const u32* __restrict__ wfrag,   // this layer's fragment array
    const float* __restrict__ bias)
{
    extern __shared__ char smraw[];
    u32*   slab_hi = (u32*)smraw;                    // [6][34][32 words] swizzled
    u32*   slab_lo = (u32*)(smraw + OFF_SLO);
    float* bias_s  = (float*)(smraw + OFF_BIAS);

    int n   = blockIdx.x;
    int t   = threadIdx.x;
    int wid = t >> 5;
    int lane = t & 31;
    int gid = lane >> 2, ctg = lane & 3;

    if (t < 64) bias_s[t] = bias[t];

    const uint2* wf2 = (const uint2*)wfrag;

    int m_lo = wid * 16 + gid;        // rows of C frags
    int m_hi = m_lo + 8;
    int row_lo = m_lo >> 5, x_lo = m_lo & 31;
    int row_hi = m_hi >> 5, x_hi = m_hi & 31;

#pragma unroll 1
    for (int it = 0; it < 8; it++) {
        __syncthreads();   // previous iteration fully consumed smem (covers bias on it=0)
        // ---- load slab rows 4it .. 4it+5 (hi and lo), x-guarded + swizzled
#pragma unroll 1
        for (int s = 0; s < 2; s++) {
            const uint4* src = (const uint4*)(s ? in_lo : in_hi);
            u32* dst = s ? slab_lo : slab_hi;
            for (int idx = t; idx < 1536; idx += 256) {
                int c  = idx & 7;
                int px = (idx >> 3) & 31;
                int r  = idx >> 8;
                uint4 v = src[((size_t)(n * 34 + it * 4 + r) * 32 + px) * 8 + c];
                int sw = ((px + 1) & 7) << 2;
                int w  = (r * 34 + px + 1) * 32 + ((c * 4) ^ sw);
                *(uint4*)(dst + w) = v;
            }
            for (int idx = t; idx < 96; idx += 256) {   // zero guards px_s = 0, 33
                int c = idx & 7;
                int side = (idx >> 3) & 1;
                int r = idx >> 4;
                int pxs = side ? 33 : 0;
                int sw = (pxs & 7) << 2;
                int w = (r * 34 + pxs) * 32 + ((c * 4) ^ sw);
                *(uint4*)(dst + w) = make_uint4(0, 0, 0, 0);
            }
        }
        __syncthreads();

        float acc[8][4];
#pragma unroll
        for (int nt = 0; nt < 8; nt++)
#pragma unroll
            for (int j = 0; j < 4; j++) acc[nt][j] = 0.f;

#pragma unroll 1
        for (int tap = 0; tap < 9; tap++) {
            int ky = tap / 3, kx = tap - ky * 3;
            int rl = row_lo + ky, pl = x_lo + kx;
            int rh = row_hi + ky, ph = x_hi + kx;
            int bl_ = (rl * 34 + pl) * 32, sl_ = (pl & 7) << 2;
            int bh_ = (rh * 34 + ph) * 32, sh_ = (ph & 7) << 2;
#pragma unroll
            for (int ks = 0; ks < 4; ks++) {
                int c0 = ks * 8 + ctg, c1 = ks * 8 + 4 + ctg;
                u32 ah[4], al[4];
                ah[0] = slab_hi[bl_ + (c0 ^ sl_)];
                ah[1] = slab_hi[bh_ + (c0 ^ sh_)];
                ah[2] = slab_hi[bl_ + (c1 ^ sl_)];
                ah[3] = slab_hi[bh_ + (c1 ^ sh_)];
                al[0] = slab_lo[bl_ + (c0 ^ sl_)];
                al[1] = slab_lo[bh_ + (c0 ^ sh_)];
                al[2] = slab_lo[bl_ + (c1 ^ sl_)];
                al[3] = slab_lo[bh_ + (c1 ^ sh_)];

                const uint2* wh = wf2 + (((tap * 2 + 0) * 4 + ks) * 8) * 32 + lane;
                const uint2* wl = wf2 + (((tap * 2 + 1) * 4 + ks) * 8) * 32 + lane;

                // pass A: hi*w_hi (keep bh2 for pass B) — 8 independent MMAs
                uint2 bh2[8];
#pragma unroll
                for (int nt = 0; nt < 8; nt++) {
                    bh2[nt] = __ldg(wh + nt * 32);
                    mma16816(acc[nt], ah, bh2[nt].x, bh2[nt].y);
                }
                // pass B: lo*w_hi — reuses bh2, 8 independent MMAs
#pragma unroll
                for (int nt = 0; nt < 8; nt++)
                    mma16816(acc[nt], al, bh2[nt].x, bh2[nt].y);
                // pass C: hi*w_lo — 8 independent MMAs
#pragma unroll
                for (int nt = 0; nt < 8; nt++) {
                    uint2 bl2 = __ldg(wl + nt * 32);
                    mma16816(acc[nt], ah, bl2.x, bl2.y);
                }
            }
        }

        // ---- epilogue: bias + ReLU, write
        int y0 = it * 4 + row_lo;
        int y1 = it * 4 + row_hi;
#pragma unroll
        for (int nt = 0; nt < 8; nt++) {
            int co = nt * 8 + ctg * 2;
            float v00 = fmaxf(acc[nt][0] + bias_s[co], 0.f);
            float v01 = fmaxf(acc[nt][1] + bias_s[co + 1], 0.f);
            float v10 = fmaxf(acc[nt][2] + bias_s[co], 0.f);
            float v11 = fmaxf(acc[nt][3] + bias_s[co + 1], 0.f);
            if (MODE == 0) {
                size_t a0 = (((size_t)n * 34 + y0 + 1) * 32 + x_lo) * 64 + co;
                size_t a1 = (((size_t)n * 34 + y1 + 1) * 32 + x_hi) * 64 + co;
                float h00 = bfhi(v00), h01 = bfhi(v01);
                float h10 = bfhi(v10), h11 = bfhi(v11);
                *(u32*)&g_s2_hi[a0] = pbf2(h00, h01);
                *(u32*)&g_s2_lo[a0] = pbf2(v00 - h00, v01 - h01);
                *(u32*)&g_s2_hi[a1] = pbf2(h10, h11);
                *(u32*)&g_s2_lo[a1] = pbf2(v10 - h10, v11 - h11);
            } else {
                size_t a0 = (((size_t)n * 32 + y0) * 32 + x_lo) * 64 + co;
                size_t a1 = (((size_t)n * 32 + y1) * 32 + x_hi) * 64 + co;
                *(float2*)&g_buf2[a0] = make_float2(v00, v01);
                *(float2*)&g_buf2[a1] = make_float2(v10, v11);
            }
        }
    }
}

// ============================================================
// Kernel 6: 3x3 VALID conv, only the selected class channel.
// grid (5, N_BOX): each block computes 6 output rows, staging 8 input rows.
// smem: ws 2304 + insm[64][8][32] 65536 + red 1024 (dynamic)
// ============================================================
#define OC_OFF_IN   2304
#define OC_OFF_RED  (2304 + 65536)
#define OC_SMEM_BYTES (2304 + 65536 + 1024)

__global__ __launch_bounds__(256) void outconv_kernel(
    const float* __restrict__ buf2,
    const float* __restrict__ ow,    // [3][3][64][3]
    const float* __restrict__ ob,
    const int*   __restrict__ cls,
    float*       __restrict__ out)   // [N][30][30]
{
    extern __shared__ char ocsm[];
    float* ws   = (float*)ocsm;                 // [9][64]
    float* insm = (float*)(ocsm + OC_OFF_IN);   // [ci][8 rows][32 px]
    float (*red)[32] = (float(*)[32])(ocsm + OC_OFF_RED);

    int n   = blockIdx.y;
    int oy0 = blockIdx.x * 6;                   // 6 output rows per block
    int t   = threadIdx.x;
    int k   = __ldg(&cls[n]);

    for (int i = t; i < 576; i += 256) ws[i] = ow[i * 3 + k];
    float bias = __ldg(&ob[k]);

    // stage input rows oy0 .. oy0+7, transposed to [ci][ry][px]
    const float4* b2 = (const float4*)buf2;
    for (int idx = t; idx < 8 * 32 * 16; idx += 256) {
        int ci4 = idx & 15;
        int rem = idx >> 4;
        int px  = rem & 31;
        int ry  = rem >> 5;
        float4 v = b2[((size_t)(n * S + oy0 + ry) * S + px) * 16 + ci4];
        int cb = ci4 * 4;
        insm[(cb + 0) * 256 + ry * 32 + px] = v.x;
        insm[(cb + 1) * 256 + ry * 32 + px] = v.y;
        insm[(cb + 2) * 256 + ry * 32 + px] = v.z;
        insm[(cb + 3) * 256 + ry * 32 + px] = v.w;
    }
    __syncthreads();

    int ox  = t & 31;
    int grp = t >> 5;

#pragma unroll 1
    for (int oyl = 0; oyl < 6; oyl++) {
        float part = 0.f;
        if (ox < OUTW) {
#pragma unroll
            for (int p = 0; p < 9; p++) {
                const int ky = p / 3, kx = p % 3;
#pragma unroll
                for (int ci = 0; ci < 8; ci++) {
                    int cig = grp * 8 + ci;
                    part += insm[cig * 256 + (oyl + ky) * 32 + ox + kx] * ws[p * 64 + cig];
                }
            }
        }
        red[grp][ox] = part;
        __syncthreads();
        if (grp == 0 && ox < OUTW) {
            float ssum = bias;
#pragma unroll
            for (int q = 0; q < 8; q++) ssum += red[q][ox];
            out[(size_t)n * (OUTW * OUTW) + (oy0 + oyl) * OUTW + ox] = ssum;
        }
        __syncthreads();
    }
}

// ============================================================
// Launch
// ============================================================
extern "C" void kernel_launch(void* const* d_in, const int* in_sizes, int n_in,
                              void* d_out, int out_size)
{
    const float* features = (const float*)d_in[0];
    const float* boxes    = (const float*)d_in[1];
    const int*   box_ids  = (const int*)d_in[2];
    const int*   cls      = (const int*)d_in[3];
    const float* w1       = (const float*)d_in[4];
    const float* b1       = (const float*)d_in[5];
    const float* w2       = (const float*)d_in[6];
    const float* b2       = (const float*)d_in[7];
    const float* ow       = (const float*)d_in[8];
    const float* ob       = (const float*)d_in[9];
    float* out = (float*)d_out;

    cudaFuncSetAttribute(conv_mma_kernel<0>,
                         cudaFuncAttributeMaxDynamicSharedMemorySize, CONV_SMEM_BYTES);
    cudaFuncSetAttribute(conv_mma_kernel<1>,
                         cudaFuncAttributeMaxDynamicSharedMemorySize, CONV_SMEM_BYTES);
    cudaFuncSetAttribute(outconv_kernel,
                         cudaFuncAttributeMaxDynamicSharedMemorySize, OC_SMEM_BYTES);

    void *s1h, *s1l, *s2h, *s2l, *wf, *p2;
    cudaGetSymbolAddress(&s1h, g_s1_hi);
    cudaGetSymbolAddress(&s1l, g_s1_lo);
    cudaGetSymbolAddress(&s2h, g_s2_hi);
    cudaGetSymbolAddress(&s2l, g_s2_lo);
    cudaGetSymbolAddress(&wf,  g_wfrag);
    cudaGetSymbolAddress(&p2,  g_buf2);

    crop_kernel<<<dim3(34, N_BOX), 256>>>(features, boxes, box_ids);
    zero_s2_guards<<<N_BOX, 256>>>();
    wprep_kernel<<<144, 256>>>(w1, w2);

    conv_mma_kernel<0><<<N_BOX, 256, CONV_SMEM_BYTES>>>(
        (const __nv_bfloat16*)s1h, (const __nv_bfloat16*)s1l,
        (const u32*)wf, b1);
    conv_mma_kernel<1><<<N_BOX, 256, CONV_SMEM_BYTES>>>(
        (const __nv_bfloat16*)s2h, (const __nv_bfloat16*)s2l,
        (const u32*)wf + 36864, b2);

    outconv_kernel<<<dim3(5, N_BOX), 256, OC_SMEM_BYTES>>>(
        (const float*)p2, ow, ob, cls, out);
}

// round 9
// speedup vs baseline: 2.5795x; 1.0818x over previous
#include <cuda_runtime.h>
#include <cuda_bf16.h>
#include <cstddef>
#include <cstdint>

typedef unsigned long long u64;
typedef unsigned int u32;

#define N_BOX 1024
#define HF 192
#define CF 64
#define S 32
#define CH 64
#define OUTW 30

// =================== static scratch ===================
// slabs: [box][34 rows][32 px][64 ch] bf16 ; rows 0,33 zero guards; row j = image row j-1
__device__ __nv_bfloat16 g_s1_hi[(size_t)N_BOX * 34 * 32 * 64];
__device__ __nv_bfloat16 g_s1_lo[(size_t)N_BOX * 34 * 32 * 64];
__device__ __nv_bfloat16 g_s2_hi[(size_t)N_BOX * 34 * 32 * 64];
__device__ __nv_bfloat16 g_s2_lo[(size_t)N_BOX * 34 * 32 * 64];
__device__ float g_buf2[(size_t)N_BOX * S * S * CH];   // conv2 out fp32
// B fragments in mma.sync register order:
// [layer][tap][split][kstep][ntile][lane] x {b0,b1} u32
__device__ u32 g_wfrag[2 * 9 * 2 * 4 * 8 * 32 * 2];

__device__ __forceinline__ u32 pbf2(float a, float b) {
    __nv_bfloat162 t = __floats2bfloat162_rn(a, b);
    return *(u32*)&t;
}
__device__ __forceinline__ float bfhi(float v) {
    return __bfloat162float(__float2bfloat16(v));
}
__device__ __forceinline__ void mma16816(float* c, const u32* a, u32 b0, u32 b1) {
    asm volatile(
        "mma.sync.aligned.m16n8k16.row.col.f32.bf16.bf16.f32 "
        "{%0,%1,%2,%3}, {%4,%5,%6,%7}, {%8,%9}, {%0,%1,%2,%3};"
        : "+f"(c[0]), "+f"(c[1]), "+f"(c[2]), "+f"(c[3])
        : "r"(a[0]), "r"(a[1]), "r"(a[2]), "r"(a[3]), "r"(b0), "r"(b1));
}
__device__ __forceinline__ void cp16(u32 dst, const void* src) {
    asm volatile("cp.async.cg.shared.global [%0], [%1], 16;" :: "r"(dst), "l"(src));
}

// ============================================================
// Kernel 1: crop_and_resize -> g_s1_hi/lo (guard rows 0/33)
// ============================================================
__global__ __launch_bounds__(256) void crop_kernel(
    const float* __restrict__ feat,
    const float* __restrict__ boxes,
    const int*   __restrict__ box_ids)
{
    int n  = blockIdx.y;
    int py = blockIdx.x;
    int t  = threadIdx.x;
    size_t rb = ((size_t)n * 34 + py) * 32 * 64;

    if (py == 0 || py == 33) {
        __nv_bfloat16 z = __float2bfloat16(0.f);
        for (int i = t; i < 32 * 64; i += 256) { g_s1_hi[rb + i] = z; g_s1_lo[rb + i] = z; }
        return;
    }
    int y = py - 1;
    float y1 = boxes[n * 4 + 0], x1 = boxes[n * 4 + 1];
    float y2 = boxes[n * 4 + 2], x2 = boxes[n * 4 + 3];
    int b = box_ids[n];

    float ty  = (float)y / (float)(S - 1);
    float ys  = (y1 + ty * (y2 - y1)) * (float)(HF - 1);
    float y0f = fminf(fmaxf(floorf(ys), 0.f), (float)(HF - 1));
    float wy  = ys - y0f;
    int y0i = (int)y0f;
    int y1i = min(y0i + 1, HF - 1);

    const float* frow0 = feat + ((size_t)(b * HF + y0i)) * HF * CF;
    const float* frow1 = feat + ((size_t)(b * HF + y1i)) * HF * CF;

    for (int i = t; i < 32 * 64; i += 256) {
        int x = i >> 6;
        int c = i & 63;
        float tx  = (float)x / (float)(S - 1);
        float xs  = (x1 + tx * (x2 - x1)) * (float)(HF - 1);
        float x0f = fminf(fmaxf(floorf(xs), 0.f), (float)(HF - 1));
        float wx  = xs - x0f;
        int x0i = (int)x0f;
        int x1i = min(x0i + 1, HF - 1);

        float v00 = frow0[x0i * CF + c];
        float v01 = frow0[x1i * CF + c];
        float v10 = frow1[x0i * CF + c];
        float v11 = frow1[x1i * CF + c];
        float top = v00 * (1.f - wx) + v01 * wx;
        float bot = v10 * (1.f - wx) + v11 * wx;
        float v   = top * (1.f - wy) + bot * wy;
        float h = bfhi(v);
        g_s1_hi[rb + i] = __float2bfloat16(h);
        g_s1_lo[rb + i] = __float2bfloat16(v - h);
    }
}

// ============================================================
// Kernel 2: zero guard rows (0, 33) of s2 slabs
// ============================================================
__global__ __launch_bounds__(256) void zero_s2_guards()
{
    int n = blockIdx.x;
    int t = threadIdx.x;
    size_t r0 = ((size_t)n * 34 + 0) * 2048;
    size_t r1 = ((size_t)n * 34 + 33) * 2048;
    __nv_bfloat16 z = __float2bfloat16(0.f);
    for (int i = t; i < 2048; i += 256) {
        g_s2_hi[r0 + i] = z; g_s2_hi[r1 + i] = z;
        g_s2_lo[r0 + i] = z; g_s2_lo[r1 + i] = z;
    }
}

// ============================================================
// Kernel 3: weight prep -> mma B-fragment order, hi/lo split
// ============================================================
__global__ __launch_bounds__(256) void wprep_kernel(
    const float* __restrict__ w1, const float* __restrict__ w2)
{
    int i = blockIdx.x * 256 + threadIdx.x;
    if (i >= 36864) return;
    int layer = i / 18432;
    int r     = i % 18432;
    int tap   = r / 2048;
    int r2    = r & 2047;
    int split = r2 >> 10;
    int ks    = (r2 >> 8) & 3;
    int nt    = (r2 >> 5) & 7;
    int lane  = r2 & 31;
    int gid = lane >> 2, ctg = lane & 3;
    int ci0 = ks * 16 + ctg * 2;
    int co  = nt * 8 + gid;
    const float* W = layer ? w2 : w1;

    float v, h, s0, s1, s2, s3;
    v = W[(tap * 64 + ci0) * 64 + co];     h = bfhi(v); s0 = split ? (v - h) : h;
    v = W[(tap * 64 + ci0 + 1) * 64 + co]; h = bfhi(v); s1 = split ? (v - h) : h;
    v = W[(tap * 64 + ci0 + 8) * 64 + co]; h = bfhi(v); s2 = split ? (v - h) : h;
    v = W[(tap * 64 + ci0 + 9) * 64 + co]; h = bfhi(v); s3 = split ? (v - h) : h;

    g_wfrag[i * 2]     = pbf2(s0, s1);
    g_wfrag[i * 2 + 1] = pbf2(s2, s3);
}

// ============================================================
// Kernel 4/5: HMMA conv 3x3 (64->64) + bias + ReLU
// CTA = one box, 256 threads (8 warps), 2 CTAs/SM.
// Double-buffered slab stages filled with cp.async (loads overlap MMAs).
// smem: 2 x (slab_hi 26112 + slab_lo 26112) + bias 256
// ============================================================
#define SPLIT_BYTES 26112
#define BUF_BYTES   52224            // hi + lo
#define OFF_BIAS    104448
#define CONV_SMEM_BYTES (104448 + 256)
#define SLAB_WORDS  6528

template <int MODE>
__global__ __launch_bounds__(256, 2) void conv_mma_kernel(
    const __nv_bfloat16* __restrict__ in_hi,
    const __nv_bfloat16* __restrict__ in_lo,
    const u32* __restrict__ wfrag,   // this layer's fragment array
    const float* __restrict__ bias)
{
    extern __shared__ char smraw[];
    float* bias_s = (float*)(smraw + OFF_BIAS);
    u32 smem_base = (u32)__cvta_generic_to_shared(smraw);

    int n   = blockIdx.x;
    int t   = threadIdx.x;
    int wid = t >> 5;
    int lane = t & 31;
    int gid = lane >> 2, ctg = lane & 3;

    if (t < 64) bias_s[t] = bias[t];

    // ---- zero x-guards (px_s = 0, 33) once for both buffers
    for (int idx = t; idx < 2 * 2 * 96; idx += 256) {
        int c    = idx & 7;
        int side = (idx >> 3) & 1;
        int r    = (idx >> 4) % 6;
        int sb   = idx / 96;                       // 0..3: buf*2+split
        int pxs  = side ? 33 : 0;
        int sw   = (pxs & 7) << 2;
        int w    = (r * 34 + pxs) * 32 + ((c * 4) ^ sw);
        u32* dst = (u32*)(smraw + sb * SPLIT_BYTES);
        *(uint4*)(dst + w) = make_uint4(0, 0, 0, 0);
    }

    const uint2* wf2 = (const uint2*)wfrag;

    int m_lo = wid * 16 + gid;
    int m_hi = m_lo + 8;
    int row_lo = m_lo >> 5, x_lo = m_lo & 31;
    int row_hi = m_hi >> 5, x_hi = m_hi & 31;

    // ---- preload helper (cp.async, 16B granules into swizzled slab)
    auto preload = [&](int itx, int sel) {
#pragma unroll 1
        for (int s = 0; s < 2; s++) {
            const uint4* src = (const uint4*)(s ? in_lo : in_hi);
            u32 dbase = smem_base + (u32)sel * BUF_BYTES + (u32)s * SPLIT_BYTES;
#pragma unroll
            for (int idx = t; idx < 1536; idx += 256) {
                int c  = idx & 7;
                int px = (idx >> 3) & 31;
                int r  = idx >> 8;
                const uint4* g = src + ((size_t)(n * 34 + itx * 4 + r) * 32 + px) * 8 + c;
                int sw = ((px + 1) & 7) << 2;
                int w  = (r * 34 + px + 1) * 32 + ((c * 4) ^ sw);
                cp16(dbase + (u32)w * 4, g);
            }
        }
    };

    preload(0, 0);
    asm volatile("cp.async.commit_group;" ::: "memory");

#pragma unroll 1
    for (int it = 0; it < 8; it++) {
        if (it < 7) {
            preload(it + 1, (it + 1) & 1);
            asm volatile("cp.async.commit_group;" ::: "memory");
            asm volatile("cp.async.wait_group 1;" ::: "memory");
        } else {
            asm volatile("cp.async.wait_group 0;" ::: "memory");
        }
        __syncthreads();   // stage `it` visible to all warps; prev compute done

        u32* slab_hi = (u32*)(smraw + (it & 1) * BUF_BYTES);
        u32* slab_lo = slab_hi + SLAB_WORDS;

        float acc[8][4];
#pragma unroll
        for (int nt = 0; nt < 8; nt++)
#pragma unroll
            for (int j = 0; j < 4; j++) acc[nt][j] = 0.f;

#pragma unroll 1
        for (int tap = 0; tap < 9; tap++) {
            int ky = tap / 3, kx = tap - ky * 3;
            int rl = row_lo + ky, pl = x_lo + kx;
            int rh = row_hi + ky, ph = x_hi + kx;
            int bl_ = (rl * 34 + pl) * 32, sl_ = (pl & 7) << 2;
            int bh_ = (rh * 34 + ph) * 32, sh_ = (ph & 7) << 2;
#pragma unroll
            for (int ks = 0; ks < 4; ks++) {
                int c0 = ks * 8 + ctg, c1 = ks * 8 + 4 + ctg;
                u32 ah[4], al[4];
                ah[0] = slab_hi[bl_ + (c0 ^ sl_)];
                ah[1] = slab_hi[bh_ + (c0 ^ sh_)];
                ah[2] = slab_hi[bl_ + (c1 ^ sl_)];
                ah[3] = slab_hi[bh_ + (c1 ^ sh_)];
                al[0] = slab_lo[bl_ + (c0 ^ sl_)];
                al[1] = slab_lo[bh_ + (c0 ^ sh_)];
                al[2] = slab_lo[bl_ + (c1 ^ sl_)];
                al[3] = slab_lo[bh_ + (c1 ^ sh_)];

                const uint2* wh = wf2 + (((tap * 2 + 0) * 4 + ks) * 8) * 32 + lane;
                const uint2* wl = wf2 + (((tap * 2 + 1) * 4 + ks) * 8) * 32 + lane;

                uint2 bh2[8];
#pragma unroll
                for (int nt = 0; nt < 8; nt++) {
                    bh2[nt] = __ldg(wh + nt * 32);
                    mma16816(acc[nt], ah, bh2[nt].x, bh2[nt].y);
                }
#pragma unroll
                for (int nt = 0; nt < 8; nt++)
                    mma16816(acc[nt], al, bh2[nt].x, bh2[nt].y);
#pragma unroll
                for (int nt = 0; nt < 8; nt++) {
                    uint2 bl2 = __ldg(wl + nt * 32);
                    mma16816(acc[nt], ah, bl2.x, bl2.y);
                }
            }
        }

        // ---- epilogue: bias + ReLU, write
        int y0 = it * 4 + row_lo;
        int y1 = it * 4 + row_hi;
#pragma unroll
        for (int nt = 0; nt < 8; nt++) {
            int co = nt * 8 + ctg * 2;
            float v00 = fmaxf(acc[nt][0] + bias_s[co], 0.f);
            float v01 = fmaxf(acc[nt][1] + bias_s[co + 1], 0.f);
            float v10 = fmaxf(acc[nt][2] + bias_s[co], 0.f);
            float v11 = fmaxf(acc[nt][3] + bias_s[co + 1], 0.f);
            if (MODE == 0) {
                size_t a0 = (((size_t)n * 34 + y0 + 1) * 32 + x_lo) * 64 + co;
                size_t a1 = (((size_t)n * 34 + y1 + 1) * 32 + x_hi) * 64 + co;
                float h00 = bfhi(v00), h01 = bfhi(v01);
                float h10 = bfhi(v10), h11 = bfhi(v11);
                *(u32*)&g_s2_hi[a0] = pbf2(h00, h01);
                *(u32*)&g_s2_lo[a0] = pbf2(v00 - h00, v01 - h01);
                *(u32*)&g_s2_hi[a1] = pbf2(h10, h11);
                *(u32*)&g_s2_lo[a1] = pbf2(v10 - h10, v11 - h11);
            } else {
                size_t a0 = (((size_t)n * 32 + y0) * 32 + x_lo) * 64 + co;
                size_t a1 = (((size_t)n * 32 + y1) * 32 + x_hi) * 64 + co;
                *(float2*)&g_buf2[a0] = make_float2(v00, v01);
                *(float2*)&g_buf2[a1] = make_float2(v10, v11);
            }
        }
        __syncthreads();   // all warps done reading this buffer before it is refilled
    }
}

// ============================================================
// Kernel 6: 3x3 VALID conv, only the selected class channel.
// grid (5, N_BOX): each block computes 6 output rows, staging 8 input rows.
// ============================================================
#define OC_OFF_IN   2304
#define OC_OFF_RED  (2304 + 65536)
#define OC_SMEM_BYTES (2304 + 65536 + 1024)

__global__ __launch_bounds__(256) void outconv_kernel(
    const float* __restrict__ buf2,
    const float* __restrict__ ow,    // [3][3][64][3]
    const float* __restrict__ ob,
    const int*   __restrict__ cls,
    float*       __restrict__ out)   // [N][30][30]
{
    extern __shared__ char ocsm[];
    float* ws   = (float*)ocsm;                 // [9][64]
    float* insm = (float*)(ocsm + OC_OFF_IN);   // [ci][8 rows][32 px]
    float (*red)[32] = (float(*)[32])(ocsm + OC_OFF_RED);

    int n   = blockIdx.y;
    int oy0 = blockIdx.x * 6;
    int t   = threadIdx.x;
    int k   = __ldg(&cls[n]);

    for (int i = t; i < 576; i += 256) ws[i] = ow[i * 3 + k];
    float bias = __ldg(&ob[k]);

    const float4* b2 = (const float4*)buf2;
    for (int idx = t; idx < 8 * 32 * 16; idx += 256) {
        int ci4 = idx & 15;
        int rem = idx >> 4;
        int px  = rem & 31;
        int ry  = rem >> 5;
        float4 v = b2[((size_t)(n * S + oy0 + ry) * S + px) * 16 + ci4];
        int cb = ci4 * 4;
        insm[(cb + 0) * 256 + ry * 32 + px] = v.x;
        insm[(cb + 1) * 256 + ry * 32 + px] = v.y;
        insm[(cb + 2) * 256 + ry * 32 + px] = v.z;
        insm[(cb + 3) * 256 + ry * 32 + px] = v.w;
    }
    __syncthreads();

    int ox  = t & 31;
    int grp = t >> 5;

#pragma unroll 1
    for (int oyl = 0; oyl < 6; oyl++) {
        float part = 0.f;
        if (ox < OUTW) {
#pragma unroll
            for (int p = 0; p < 9; p++) {
                const int ky = p / 3, kx = p % 3;
#pragma unroll
                for (int ci = 0; ci < 8; ci++) {
                    int cig = grp * 8 + ci;
                    part += insm[cig * 256 + (oyl + ky) * 32 + ox + kx] * ws[p * 64 + cig];
                }
            }
        }
        red[grp][ox] = part;
        __syncthreads();
        if (grp == 0 && ox < OUTW) {
            float ssum = bias;
#pragma unroll
            for (int q = 0; q < 8; q++) ssum += red[q][ox];
            out[(size_t)n * (OUTW * OUTW) + (oy0 + oyl) * OUTW + ox] = ssum;
        }
        __syncthreads();
    }
}

// ============================================================
// Launch
// ============================================================
extern "C" void kernel_launch(void* const* d_in, const int* in_sizes, int n_in,
                              void* d_out, int out_size)
{
    const float* features = (const float*)d_in[0];
    const float* boxes    = (const float*)d_in[1];
    const int*   box_ids  = (const int*)d_in[2];
    const int*   cls      = (const int*)d_in[3];
    const float* w1       = (const float*)d_in[4];
    const float* b1       = (const float*)d_in[5];
    const float* w2       = (const float*)d_in[6];
    const float* b2       = (const float*)d_in[7];
    const float* ow       = (const float*)d_in[8];
    const float* ob       = (const float*)d_in[9];
    float* out = (float*)d_out;

    cudaFuncSetAttribute(conv_mma_kernel<0>,
                         cudaFuncAttributeMaxDynamicSharedMemorySize, CONV_SMEM_BYTES);
    cudaFuncSetAttribute(conv_mma_kernel<1>,
                         cudaFuncAttributeMaxDynamicSharedMemorySize, CONV_SMEM_BYTES);
    cudaFuncSetAttribute(outconv_kernel,
                         cudaFuncAttributeMaxDynamicSharedMemorySize, OC_SMEM_BYTES);

    void *s1h, *s1l, *s2h, *s2l, *wf, *p2;
    cudaGetSymbolAddress(&s1h, g_s1_hi);
    cudaGetSymbolAddress(&s1l, g_s1_lo);
    cudaGetSymbolAddress(&s2h, g_s2_hi);
    cudaGetSymbolAddress(&s2l, g_s2_lo);
    cudaGetSymbolAddress(&wf,  g_wfrag);
    cudaGetSymbolAddress(&p2,  g_buf2);

    crop_kernel<<<dim3(34, N_BOX), 256>>>(features, boxes, box_ids);
    zero_s2_guards<<<N_BOX, 256>>>();
    wprep_kernel<<<144, 256>>>(w1, w2);

    conv_mma_kernel<0><<<N_BOX, 256, CONV_SMEM_BYTES>>>(
        (const __nv_bfloat16*)s1h, (const __nv_bfloat16*)s1l,
        (const u32*)wf, b1);
    conv_mma_kernel<1><<<N_BOX, 256, CONV_SMEM_BYTES>>>(
        (const __nv_bfloat16*)s2h, (const __nv_bfloat16*)s2l,
        (const u32*)wf + 36864, b2);

    outconv_kernel<<<dim3(5, N_BOX), 256, OC_SMEM_BYTES>>>(
        (const float*)p2, ow, ob, cls, out);
}

// round 10
// speedup vs baseline: 3.5421x; 1.3732x over previous
#include <cuda_runtime.h>
#include <cuda_fp16.h>
#include <cstddef>
#include <cstdint>

typedef unsigned long long u64;
typedef unsigned int u32;

#define N_BOX 1024
#define HF 192
#define CF 64
#define S 32
#define CH 64
#define OUTW 30

// =================== static scratch ===================
// slabs: [box][34 rows][32 px][64 ch] fp16 ; rows 0,33 zero guards; row j = image row j-1
__device__ __half g_s1_hi[(size_t)N_BOX * 34 * 32 * 64];
__device__ __half g_s1_lo[(size_t)N_BOX * 34 * 32 * 64];
__device__ __half g_s2_hi[(size_t)N_BOX * 34 * 32 * 64];
__device__ __half g_s2_lo[(size_t)N_BOX * 34 * 32 * 64];
__device__ __half g_buf2[(size_t)N_BOX * S * S * CH];   // conv2 out fp16
// B fragments (single fp16 weights) in mma.sync register order:
// [layer][tap][kstep][ntile][lane] x {b0,b1} u32
__device__ u32 g_wfrag[2 * 9 * 4 * 8 * 32 * 2];

__device__ __forceinline__ u32 ph2(float a, float b) {
    __half2 t = __floats2half2_rn(a, b);
    return *(u32*)&t;
}
__device__ __forceinline__ void mma16816(float* c, const u32* a, u32 b0, u32 b1) {
    asm volatile(
        "mma.sync.aligned.m16n8k16.row.col.f32.f16.f16.f32 "
        "{%0,%1,%2,%3}, {%4,%5,%6,%7}, {%8,%9}, {%0,%1,%2,%3};"
        : "+f"(c[0]), "+f"(c[1]), "+f"(c[2]), "+f"(c[3])
        : "r"(a[0]), "r"(a[1]), "r"(a[2]), "r"(a[3]), "r"(b0), "r"(b1));
}
__device__ __forceinline__ void cp16(u32 dst, const void* src) {
    asm volatile("cp.async.cg.shared.global [%0], [%1], 16;" :: "r"(dst), "l"(src));
}

// ============================================================
// Kernel 1: crop_and_resize -> g_s1_hi/lo (guard rows 0/33)
// ============================================================
__global__ __launch_bounds__(256) void crop_kernel(
    const float* __restrict__ feat,
    const float* __restrict__ boxes,
    const int*   __restrict__ box_ids)
{
    int n  = blockIdx.y;
    int py = blockIdx.x;
    int t  = threadIdx.x;
    size_t rb = ((size_t)n * 34 + py) * 32 * 64;

    if (py == 0 || py == 33) {
        __half z = __float2half(0.f);
        for (int i = t; i < 32 * 64; i += 256) { g_s1_hi[rb + i] = z; g_s1_lo[rb + i] = z; }
        return;
    }
    int y = py - 1;
    float y1 = boxes[n * 4 + 0], x1 = boxes[n * 4 + 1];
    float y2 = boxes[n * 4 + 2], x2 = boxes[n * 4 + 3];
    int b = box_ids[n];

    float ty  = (float)y / (float)(S - 1);
    float ys  = (y1 + ty * (y2 - y1)) * (float)(HF - 1);
    float y0f = fminf(fmaxf(floorf(ys), 0.f), (float)(HF - 1));
    float wy  = ys - y0f;
    int y0i = (int)y0f;
    int y1i = min(y0i + 1, HF - 1);

    const float* frow0 = feat + ((size_t)(b * HF + y0i)) * HF * CF;
    const float* frow1 = feat + ((size_t)(b * HF + y1i)) * HF * CF;

    for (int i = t; i < 32 * 64; i += 256) {
        int x = i >> 6;
        int c = i & 63;
        float tx  = (float)x / (float)(S - 1);
        float xs  = (x1 + tx * (x2 - x1)) * (float)(HF - 1);
        float x0f = fminf(fmaxf(floorf(xs), 0.f), (float)(HF - 1));
        float wx  = xs - x0f;
        int x0i = (int)x0f;
        int x1i = min(x0i + 1, HF - 1);

        float v00 = frow0[x0i * CF + c];
        float v01 = frow0[x1i * CF + c];
        float v10 = frow1[x0i * CF + c];
        float v11 = frow1[x1i * CF + c];
        float top = v00 * (1.f - wx) + v01 * wx;
        float bot = v10 * (1.f - wx) + v11 * wx;
        float v   = top * (1.f - wy) + bot * wy;
        __half h = __float2half_rn(v);
        g_s1_hi[rb + i] = h;
        g_s1_lo[rb + i] = __float2half_rn(v - __half2float(h));
    }
}

// ============================================================
// Kernel 2: zero guard rows (0, 33) of s2 slabs
// ============================================================
__global__ __launch_bounds__(256) void zero_s2_guards()
{
    int n = blockIdx.x;
    int t = threadIdx.x;
    size_t r0 = ((size_t)n * 34 + 0) * 2048;
    size_t r1 = ((size_t)n * 34 + 33) * 2048;
    __half z = __float2half(0.f);
    for (int i = t; i < 2048; i += 256) {
        g_s2_hi[r0 + i] = z; g_s2_hi[r1 + i] = z;
        g_s2_lo[r0 + i] = z; g_s2_lo[r1 + i] = z;
    }
}

// ============================================================
// Kernel 3: weight prep -> mma B-fragment order, single fp16
// ============================================================
__global__ __launch_bounds__(256) void wprep_kernel(
    const float* __restrict__ w1, const float* __restrict__ w2)
{
    int i = blockIdx.x * 256 + threadIdx.x;
    if (i >= 18432) return;                  // 2 layers * 9 * 4 * 8 * 32
    int layer = i / 9216;
    int r     = i % 9216;
    int tap   = r / 1024;
    int r2    = r & 1023;
    int ks    = (r2 >> 8) & 3;
    int nt    = (r2 >> 5) & 7;
    int lane  = r2 & 31;
    int gid = lane >> 2, ctg = lane & 3;
    int ci0 = ks * 16 + ctg * 2;
    int co  = nt * 8 + gid;
    const float* W = layer ? w2 : w1;

    g_wfrag[i * 2]     = ph2(W[(tap * 64 + ci0) * 64 + co],
                             W[(tap * 64 + ci0 + 1) * 64 + co]);
    g_wfrag[i * 2 + 1] = ph2(W[(tap * 64 + ci0 + 8) * 64 + co],
                             W[(tap * 64 + ci0 + 9) * 64 + co]);
}

// ============================================================
// Kernel 4/5: HMMA conv 3x3 (64->64) + bias + ReLU  (fp16 2-pass)
// CTA = one box, 256 threads (8 warps), 2 CTAs/SM.
// Double-buffered slab stages filled with cp.async.
// ============================================================
#define SPLIT_BYTES 26112
#define BUF_BYTES   52224            // hi + lo
#define OFF_BIAS    104448
#define CONV_SMEM_BYTES (104448 + 256)
#define SLAB_WORDS  6528

template <int MODE>
__global__ __launch_bounds__(256, 2) void conv_mma_kernel(
    const __half* __restrict__ in_hi,
    const __half* __restrict__ in_lo,
    const u32* __restrict__ wfrag,   // this layer's fragment array
    const float* __restrict__ bias)
{
    extern __shared__ char smraw[];
    float* bias_s = (float*)(smraw + OFF_BIAS);
    u32 smem_base = (u32)__cvta_generic_to_shared(smraw);

    int n   = blockIdx.x;
    int t   = threadIdx.x;
    int wid = t >> 5;
    int lane = t & 31;
    int gid = lane >> 2, ctg = lane & 3;

    if (t < 64) bias_s[t] = bias[t];

    // ---- zero x-guards (px_s = 0, 33) once for both buffers
    for (int idx = t; idx < 2 * 2 * 96; idx += 256) {
        int c    = idx & 7;
        int side = (idx >> 3) & 1;
        int r    = (idx >> 4) % 6;
        int sb   = idx / 96;
        int pxs  = side ? 33 : 0;
        int sw   = (pxs & 7) << 2;
        int w    = (r * 34 + pxs) * 32 + ((c * 4) ^ sw);
        u32* dst = (u32*)(smraw + sb * SPLIT_BYTES);
        *(uint4*)(dst + w) = make_uint4(0, 0, 0, 0);
    }

    const uint2* wf2 = (const uint2*)wfrag;

    int m_lo = wid * 16 + gid;
    int m_hi = m_lo + 8;
    int row_lo = m_lo >> 5, x_lo = m_lo & 31;
    int row_hi = m_hi >> 5, x_hi = m_hi & 31;

    auto preload = [&](int itx, int sel) {
#pragma unroll 1
        for (int s = 0; s < 2; s++) {
            const uint4* src = (const uint4*)(s ? in_lo : in_hi);
            u32 dbase = smem_base + (u32)sel * BUF_BYTES + (u32)s * SPLIT_BYTES;
#pragma unroll
            for (int idx = t; idx < 1536; idx += 256) {
                int c  = idx & 7;
                int px = (idx >> 3) & 31;
                int r  = idx >> 8;
                const uint4* g = src + ((size_t)(n * 34 + itx * 4 + r) * 32 + px) * 8 + c;
                int sw = ((px + 1) & 7) << 2;
                int w  = (r * 34 + px + 1) * 32 + ((c * 4) ^ sw);
                cp16(dbase + (u32)w * 4, g);
            }
        }
    };

    preload(0, 0);
    asm volatile("cp.async.commit_group;" ::: "memory");

#pragma unroll 1
    for (int it = 0; it < 8; it++) {
        if (it < 7) {
            preload(it + 1, (it + 1) & 1);
            asm volatile("cp.async.commit_group;" ::: "memory");
            asm volatile("cp.async.wait_group 1;" ::: "memory");
        } else {
            asm volatile("cp.async.wait_group 0;" ::: "memory");
        }
        __syncthreads();

        u32* slab_hi = (u32*)(smraw + (it & 1) * BUF_BYTES);
        u32* slab_lo = slab_hi + SLAB_WORDS;

        float acc[8][4];
#pragma unroll
        for (int nt = 0; nt < 8; nt++)
#pragma unroll
            for (int j = 0; j < 4; j++) acc[nt][j] = 0.f;

#pragma unroll 1
        for (int tap = 0; tap < 9; tap++) {
            int ky = tap / 3, kx = tap - ky * 3;
            int rl = row_lo + ky, pl = x_lo + kx;
            int rh = row_hi + ky, ph = x_hi + kx;
            int bl_ = (rl * 34 + pl) * 32, sl_ = (pl & 7) << 2;
            int bh_ = (rh * 34 + ph) * 32, sh_ = (ph & 7) << 2;
#pragma unroll
            for (int ks = 0; ks < 4; ks++) {
                int c0 = ks * 8 + ctg, c1 = ks * 8 + 4 + ctg;
                u32 ah[4], al[4];
                ah[0] = slab_hi[bl_ + (c0 ^ sl_)];
                ah[1] = slab_hi[bh_ + (c0 ^ sh_)];
                ah[2] = slab_hi[bl_ + (c1 ^ sl_)];
                ah[3] = slab_hi[bh_ + (c1 ^ sh_)];
                al[0] = slab_lo[bl_ + (c0 ^ sl_)];
                al[1] = slab_lo[bh_ + (c0 ^ sh_)];
                al[2] = slab_lo[bl_ + (c1 ^ sl_)];
                al[3] = slab_lo[bh_ + (c1 ^ sh_)];

                const uint2* wh = wf2 + ((tap * 4 + ks) * 8) * 32 + lane;

                // pass A: a_hi * w (keep frags for pass B)
                uint2 bw[8];
#pragma unroll
                for (int nt = 0; nt < 8; nt++) {
                    bw[nt] = __ldg(wh + nt * 32);
                    mma16816(acc[nt], ah, bw[nt].x, bw[nt].y);
                }
                // pass B: a_lo * w
#pragma unroll
                for (int nt = 0; nt < 8; nt++)
                    mma16816(acc[nt], al, bw[nt].x, bw[nt].y);
            }
        }

        // ---- epilogue: bias + ReLU, write
        int y0 = it * 4 + row_lo;
        int y1 = it * 4 + row_hi;
#pragma unroll
        for (int nt = 0; nt < 8; nt++) {
            int co = nt * 8 + ctg * 2;
            float v00 = fmaxf(acc[nt][0] + bias_s[co], 0.f);
            float v01 = fmaxf(acc[nt][1] + bias_s[co + 1], 0.f);
            float v10 = fmaxf(acc[nt][2] + bias_s[co], 0.f);
            float v11 = fmaxf(acc[nt][3] + bias_s[co + 1], 0.f);
            if (MODE == 0) {
                size_t a0 = (((size_t)n * 34 + y0 + 1) * 32 + x_lo) * 64 + co;
                size_t a1 = (((size_t)n * 34 + y1 + 1) * 32 + x_hi) * 64 + co;
                __half h00 = __float2half_rn(v00), h01 = __float2half_rn(v01);
                __half h10 = __float2half_rn(v10), h11 = __float2half_rn(v11);
                __half2 H0; H0.x = h00; H0.y = h01;
                __half2 H1; H1.x = h10; H1.y = h11;
                *(__half2*)&g_s2_hi[a0] = H0;
                *(u32*)&g_s2_lo[a0] = ph2(v00 - __half2float(h00), v01 - __half2float(h01));
                *(__half2*)&g_s2_hi[a1] = H1;
                *(u32*)&g_s2_lo[a1] = ph2(v10 - __half2float(h10), v11 - __half2float(h11));
            } else {
                size_t a0 = (((size_t)n * 32 + y0) * 32 + x_lo) * 64 + co;
                size_t a1 = (((size_t)n * 32 + y1) * 32 + x_hi) * 64 + co;
                *(u32*)&g_buf2[a0] = ph2(v00, v01);
                *(u32*)&g_buf2[a1] = ph2(v10, v11);
            }
        }
        __syncthreads();
    }
}

// ============================================================
// Kernel 6: 3x3 VALID conv, only the selected class channel.
// grid (5, N_BOX): each block computes 6 output rows, staging 8 input rows.
// ============================================================
#define OC_OFF_IN   2304
#define OC_OFF_RED  (2304 + 65536)
#define OC_SMEM_BYTES (2304 + 65536 + 1024)

__global__ __launch_bounds__(256) void outconv_kernel(
    const __half* __restrict__ buf2,
    const float* __restrict__ ow,    // [3][3][64][3]
    const float* __restrict__ ob,
    const int*   __restrict__ cls,
    float*       __restrict__ out)   // [N][30][30]
{
    extern __shared__ char ocsm[];
    float* ws   = (float*)ocsm;                 // [9][64]
    float* insm = (float*)(ocsm + OC_OFF_IN);   // [ci][8 rows][32 px]
    float (*red)[32] = (float(*)[32])(ocsm + OC_OFF_RED);

    int n   = blockIdx.y;
    int oy0 = blockIdx.x * 6;
    int t   = threadIdx.x;
    int k   = __ldg(&cls[n]);

    for (int i = t; i < 576; i += 256) ws[i] = ow[i * 3 + k];
    float bias = __ldg(&ob[k]);

    // stage input rows oy0..oy0+7, fp16 -> fp32, transposed to [ci][ry][px]
    const uint4* b2 = (const uint4*)buf2;       // 8 halves per uint4
    for (int idx = t; idx < 8 * 32 * 8; idx += 256) {
        int c  = idx & 7;                       // channel chunk (8 ch)
        int px = (idx >> 3) & 31;
        int ry = idx >> 8;
        uint4 v = b2[((size_t)(n * S + oy0 + ry) * S + px) * 8 + c];
        const __half2* hp = (const __half2*)&v;
#pragma unroll
        for (int j = 0; j < 4; j++) {
            float2 f = __half22float2(hp[j]);
            insm[(c * 8 + j * 2 + 0) * 256 + ry * 32 + px] = f.x;
            insm[(c * 8 + j * 2 + 1) * 256 + ry * 32 + px] = f.y;
        }
    }
    __syncthreads();

    int ox  = t & 31;
    int grp = t >> 5;

#pragma unroll 1
    for (int oyl = 0; oyl < 6; oyl++) {
        float part = 0.f;
        if (ox < OUTW) {
#pragma unroll
            for (int p = 0; p < 9; p++) {
                const int ky = p / 3, kx = p % 3;
#pragma unroll
                for (int ci = 0; ci < 8; ci++) {
                    int cig = grp * 8 + ci;
                    part += insm[cig * 256 + (oyl + ky) * 32 + ox + kx] * ws[p * 64 + cig];
                }
            }
        }
        red[grp][ox] = part;
        __syncthreads();
        if (grp == 0 && ox < OUTW) {
            float ssum = bias;
#pragma unroll
            for (int q = 0; q < 8; q++) ssum += red[q][ox];
            out[(size_t)n * (OUTW * OUTW) + (oy0 + oyl) * OUTW + ox] = ssum;
        }
        __syncthreads();
    }
}

// ============================================================
// Launch
// ============================================================
extern "C" void kernel_launch(void* const* d_in, const int* in_sizes, int n_in,
                              void* d_out, int out_size)
{
    const float* features = (const float*)d_in[0];
    const float* boxes    = (const float*)d_in[1];
    const int*   box_ids  = (const int*)d_in[2];
    const int*   cls      = (const int*)d_in[3];
    const float* w1       = (const float*)d_in[4];
    const float* b1       = (const float*)d_in[5];
    const float* w2       = (const float*)d_in[6];
    const float* b2       = (const float*)d_in[7];
    const float* ow       = (const float*)d_in[8];
    const float* ob       = (const float*)d_in[9];
    float* out = (float*)d_out;

    cudaFuncSetAttribute(conv_mma_kernel<0>,
                         cudaFuncAttributeMaxDynamicSharedMemorySize, CONV_SMEM_BYTES);
    cudaFuncSetAttribute(conv_mma_kernel<1>,
                         cudaFuncAttributeMaxDynamicSharedMemorySize, CONV_SMEM_BYTES);
    cudaFuncSetAttribute(outconv_kernel,
                         cudaFuncAttributeMaxDynamicSharedMemorySize, OC_SMEM_BYTES);

    void *s1h, *s1l, *s2h, *s2l, *wf, *p2;
    cudaGetSymbolAddress(&s1h, g_s1_hi);
    cudaGetSymbolAddress(&s1l, g_s1_lo);
    cudaGetSymbolAddress(&s2h, g_s2_hi);
    cudaGetSymbolAddress(&s2l, g_s2_lo);
    cudaGetSymbolAddress(&wf,  g_wfrag);
    cudaGetSymbolAddress(&p2,  g_buf2);

    crop_kernel<<<dim3(34, N_BOX), 256>>>(features, boxes, box_ids);
    zero_s2_guards<<<N_BOX, 256>>>();
    wprep_kernel<<<72, 256>>>(w1, w2);

    conv_mma_kernel<0><<<N_BOX, 256, CONV_SMEM_BYTES>>>(
        (const __half*)s1h, (const __half*)s1l,
        (const u32*)wf, b1);
    conv_mma_kernel<1><<<N_BOX, 256, CONV_SMEM_BYTES>>>(
        (const __half*)s2h, (const __half*)s2l,
        (const u32*)wf + 18432, b2);

    outconv_kernel<<<dim3(5, N_BOX), 256, OC_SMEM_BYTES>>>(
        (const __half*)p2, ow, ob, cls, out);
}

// round 11
// speedup vs baseline: 4.4459x; 1.2552x over previous
#include <cuda_runtime.h>
#include <cuda_fp16.h>
#include <cstddef>
#include <cstdint>

typedef unsigned long long u64;
typedef unsigned int u32;

#define N_BOX 1024
#define HF 192
#define CF 64
#define S 32
#define CH 64
#define OUTW 30

// =================== static scratch ===================
// g_s2: conv1 out, [box][34 rows][32 px][64 ch] fp16, rows 0/33 zero guards
__device__ __half g_s2[(size_t)N_BOX * 34 * 32 * 64];
__device__ __half g_buf2[(size_t)N_BOX * S * S * CH];   // conv2 out fp16
// B fragments (single fp16 weights) in mma.sync register order:
// [layer][tap][kstep][ntile][lane] x {b0,b1} u32
__device__ u32 g_wfrag[2 * 9 * 4 * 8 * 32 * 2];

__device__ __forceinline__ u32 ph2(float a, float b) {
    __half2 t = __floats2half2_rn(a, b);
    return *(u32*)&t;
}
__device__ __forceinline__ void mma16816(float* c, const u32* a, u32 b0, u32 b1) {
    asm volatile(
        "mma.sync.aligned.m16n8k16.row.col.f32.f16.f16.f32 "
        "{%0,%1,%2,%3}, {%4,%5,%6,%7}, {%8,%9}, {%0,%1,%2,%3};"
        : "+f"(c[0]), "+f"(c[1]), "+f"(c[2]), "+f"(c[3])
        : "r"(a[0]), "r"(a[1]), "r"(a[2]), "r"(a[3]), "r"(b0), "r"(b1));
}
__device__ __forceinline__ void cp16(u32 dst, const void* src) {
    asm volatile("cp.async.cg.shared.global [%0], [%1], 16;" :: "r"(dst), "l"(src));
}

// ============================================================
// Kernel A: zero guard rows (0, 33) of g_s2
// ============================================================
__global__ __launch_bounds__(256) void zero_s2_guards()
{
    int n = blockIdx.x;
    int t = threadIdx.x;
    size_t r0 = ((size_t)n * 34 + 0) * 2048;
    size_t r1 = ((size_t)n * 34 + 33) * 2048;
    __half z = __float2half(0.f);
    for (int i = t; i < 2048; i += 256) {
        g_s2[r0 + i] = z; g_s2[r1 + i] = z;
    }
}

// ============================================================
// Kernel B: weight prep -> mma B-fragment order, single fp16
// ============================================================
__global__ __launch_bounds__(256) void wprep_kernel(
    const float* __restrict__ w1, const float* __restrict__ w2)
{
    int i = blockIdx.x * 256 + threadIdx.x;
    if (i >= 18432) return;                  // 2 layers * 9 * 4 * 8 * 32
    int layer = i / 9216;
    int r     = i % 9216;
    int tap   = r / 1024;
    int r2    = r & 1023;
    int ks    = (r2 >> 8) & 3;
    int nt    = (r2 >> 5) & 7;
    int lane  = r2 & 31;
    int gid = lane >> 2, ctg = lane & 3;
    int ci0 = ks * 16 + ctg * 2;
    int co  = nt * 8 + gid;
    const float* W = layer ? w2 : w1;

    g_wfrag[i * 2]     = ph2(W[(tap * 64 + ci0) * 64 + co],
                             W[(tap * 64 + ci0 + 1) * 64 + co]);
    g_wfrag[i * 2 + 1] = ph2(W[(tap * 64 + ci0 + 8) * 64 + co],
                             W[(tap * 64 + ci0 + 9) * 64 + co]);
}

// ============================================================
// Kernel C: conv1 with FUSED crop_and_resize.
// CTA = one box, 256 threads (8 warps), 2 CTAs/SM.
// Per 4-row stage: bilinear-gather features -> hi/lo fp16 slab in smem
// (double-buffered, one sync per stage), then 2-pass fp16 HMMA,
// epilogue writes single-fp16 g_s2 (rows +1).
// smem: 2 x (slab_hi 26112 + slab_lo 26112) + bias 256
// ============================================================
#define SPLIT_BYTES 26112
#define BUF_BYTES   52224
#define C1_OFF_BIAS 104448
#define C1_SMEM_BYTES (104448 + 256)
#define SLAB_WORDS  6528

__global__ __launch_bounds__(256, 2) void conv1_kernel(
    const float* __restrict__ feat,
    const float* __restrict__ boxes,
    const int*   __restrict__ box_ids,
    const u32*   __restrict__ wfrag,
    const float* __restrict__ bias)
{
    extern __shared__ char smraw[];
    float* bias_s = (float*)(smraw + C1_OFF_BIAS);

    int n   = blockIdx.x;
    int t   = threadIdx.x;
    int wid = t >> 5;
    int lane = t & 31;
    int gid = lane >> 2, ctg = lane & 3;

    if (t < 64) bias_s[t] = bias[t];

    // box params
    float y1 = boxes[n * 4 + 0], x1 = boxes[n * 4 + 1];
    float y2 = boxes[n * 4 + 2], x2 = boxes[n * 4 + 3];
    int b = box_ids[n];
    const float4* f4 = (const float4*)(feat + (size_t)b * HF * HF * CF);

    // ---- zero x-guards (px_s = 0, 33) once, both buffers both splits
    for (int idx = t; idx < 2 * 2 * 96; idx += 256) {
        int c    = idx & 7;
        int side = (idx >> 3) & 1;
        int r    = (idx >> 4) % 6;
        int sb   = idx / 96;
        int pxs  = side ? 33 : 0;
        int sw   = (pxs & 7) << 2;
        int w    = (r * 34 + pxs) * 32 + ((c * 4) ^ sw);
        u32* dst = (u32*)(smraw + sb * SPLIT_BYTES);
        *(uint4*)(dst + w) = make_uint4(0, 0, 0, 0);
    }

    const uint2* wf2 = (const uint2*)wfrag;

    // crop-thread mapping: px = t>>3 (0..31), cg = t&7 (2 chunks of 4 ch)
    int cpx = t >> 3;
    int cg  = t & 7;
    float xs  = (x1 + (float)cpx * (1.f / 31.f) * (x2 - x1)) * (float)(HF - 1);
    float x0f = fminf(fmaxf(floorf(xs), 0.f), (float)(HF - 1));
    float wx  = xs - x0f;
    int x0i = (int)x0f;
    int x1i = min(x0i + 1, HF - 1);
    int csw = ((cpx + 1) & 7) << 2;

    // MMA tile mapping
    int m_lo = wid * 16 + gid;
    int m_hi = m_lo + 8;
    int row_lo = m_lo >> 5, x_lo = m_lo & 31;
    int row_hi = m_hi >> 5, x_hi = m_hi & 31;

#pragma unroll 1
    for (int it = 0; it < 8; it++) {
        // ---- fused crop: fill stage `it` slab (buffer it&1)
        {
            u32* shi = (u32*)(smraw + (it & 1) * BUF_BYTES);
            u32* slo = shi + SLAB_WORDS;
#pragma unroll
            for (int r = 0; r < 6; r++) {
                int j  = it * 4 + r;                      // 0..33
                float wz = (j == 0 || j == 33) ? 0.f : 1.f;
                int y  = min(max(j - 1, 0), S - 1);
                float ys  = (y1 + (float)y * (1.f / 31.f) * (y2 - y1)) * (float)(HF - 1);
                float y0f = fminf(fmaxf(floorf(ys), 0.f), (float)(HF - 1));
                float wy  = ys - y0f;
                int y0i = (int)y0f;
                int y1i = min(y0i + 1, HF - 1);
                const float4* r0 = f4 + (size_t)y0i * HF * 16;
                const float4* r1 = f4 + (size_t)y1i * HF * 16;
                int base = (r * 34 + cpx + 1) * 32;
                float omx = 1.f - wx, omy = 1.f - wy;
#pragma unroll
                for (int q = 0; q < 2; q++) {
                    int ck = cg * 2 + q;                  // 4-channel chunk
                    float4 v00 = r0[x0i * 16 + ck];
                    float4 v01 = r0[x1i * 16 + ck];
                    float4 v10 = r1[x0i * 16 + ck];
                    float4 v11 = r1[x1i * 16 + ck];
                    float o[4];
                    o[0] = ((v00.x * omx + v01.x * wx) * omy + (v10.x * omx + v11.x * wx) * wy) * wz;
                    o[1] = ((v00.y * omx + v01.y * wx) * omy + (v10.y * omx + v11.y * wx) * wy) * wz;
                    o[2] = ((v00.z * omx + v01.z * wx) * omy + (v10.z * omx + v11.z * wx) * wy) * wz;
                    o[3] = ((v00.w * omx + v01.w * wx) * omy + (v10.w * omx + v11.w * wx) * wy) * wz;
                    __half h[4];
                    float  l[4];
#pragma unroll
                    for (int e = 0; e < 4; e++) {
                        h[e] = __float2half_rn(o[e]);
                        l[e] = o[e] - __half2float(h[e]);
                    }
                    int w = base + ((ck * 2) ^ csw);
                    uint2 Hh, Ll;
                    Hh.x = ph2(__half2float(h[0]), __half2float(h[1]));
                    Hh.y = ph2(__half2float(h[2]), __half2float(h[3]));
                    Ll.x = ph2(l[0], l[1]);
                    Ll.y = ph2(l[2], l[3]);
                    *(uint2*)(shi + w) = Hh;
                    *(uint2*)(slo + w) = Ll;
                }
            }
        }
        __syncthreads();   // slab `it` complete; prev iter's other buffer free

        u32* slab_hi = (u32*)(smraw + (it & 1) * BUF_BYTES);
        u32* slab_lo = slab_hi + SLAB_WORDS;

        float acc[8][4];
#pragma unroll
        for (int nt = 0; nt < 8; nt++)
#pragma unroll
            for (int j = 0; j < 4; j++) acc[nt][j] = 0.f;

#pragma unroll 1
        for (int tap = 0; tap < 9; tap++) {
            int ky = tap / 3, kx = tap - ky * 3;
            int rl = row_lo + ky, pl = x_lo + kx;
            int rh = row_hi + ky, ph = x_hi + kx;
            int bl_ = (rl * 34 + pl) * 32, sl_ = (pl & 7) << 2;
            int bh_ = (rh * 34 + ph) * 32, sh_ = (ph & 7) << 2;
#pragma unroll
            for (int ks = 0; ks < 4; ks++) {
                int c0 = ks * 8 + ctg, c1 = ks * 8 + 4 + ctg;
                u32 ah[4], al[4];
                ah[0] = slab_hi[bl_ + (c0 ^ sl_)];
                ah[1] = slab_hi[bh_ + (c0 ^ sh_)];
                ah[2] = slab_hi[bl_ + (c1 ^ sl_)];
                ah[3] = slab_hi[bh_ + (c1 ^ sh_)];
                al[0] = slab_lo[bl_ + (c0 ^ sl_)];
                al[1] = slab_lo[bh_ + (c0 ^ sh_)];
                al[2] = slab_lo[bl_ + (c1 ^ sl_)];
                al[3] = slab_lo[bh_ + (c1 ^ sh_)];

                const uint2* wh = wf2 + ((tap * 4 + ks) * 8) * 32 + lane;

                uint2 bw[8];
#pragma unroll
                for (int nt = 0; nt < 8; nt++) {
                    bw[nt] = __ldg(wh + nt * 32);
                    mma16816(acc[nt], ah, bw[nt].x, bw[nt].y);
                }
#pragma unroll
                for (int nt = 0; nt < 8; nt++)
                    mma16816(acc[nt], al, bw[nt].x, bw[nt].y);
            }
        }

        // ---- epilogue: bias + ReLU, single-fp16 write to g_s2 (rows +1)
        int y0 = it * 4 + row_lo;
        int y1r = it * 4 + row_hi;
#pragma unroll
        for (int nt = 0; nt < 8; nt++) {
            int co = nt * 8 + ctg * 2;
            float v00 = fmaxf(acc[nt][0] + bias_s[co], 0.f);
            float v01 = fmaxf(acc[nt][1] + bias_s[co + 1], 0.f);
            float v10 = fmaxf(acc[nt][2] + bias_s[co], 0.f);
            float v11 = fmaxf(acc[nt][3] + bias_s[co + 1], 0.f);
            size_t a0 = (((size_t)n * 34 + y0 + 1) * 32 + x_lo) * 64 + co;
            size_t a1 = (((size_t)n * 34 + y1r + 1) * 32 + x_hi) * 64 + co;
            *(u32*)&g_s2[a0] = ph2(v00, v01);
            *(u32*)&g_s2[a1] = ph2(v10, v11);
        }
        // no second sync: double buffer, next crop targets the other buffer
    }
}

// ============================================================
// Kernel D: conv2, single-pass fp16 HMMA (activations rounded once).
// cp.async double-buffered single-split slab. 2 CTAs/SM.
// smem: 2 x 26112 + bias 256
// ============================================================
#define C2_OFF_BIAS 52224
#define C2_SMEM_BYTES (52224 + 256)

__global__ __launch_bounds__(256, 2) void conv2_kernel(
    const __half* __restrict__ in,        // g_s2
    const u32*    __restrict__ wfrag,     // layer-1 fragment array
    const float*  __restrict__ bias)
{
    extern __shared__ char smraw[];
    float* bias_s = (float*)(smraw + C2_OFF_BIAS);
    u32 smem_base = (u32)__cvta_generic_to_shared(smraw);

    int n   = blockIdx.x;
    int t   = threadIdx.x;
    int wid = t >> 5;
    int lane = t & 31;
    int gid = lane >> 2, ctg = lane & 3;

    if (t < 64) bias_s[t] = bias[t];

    // zero x-guards for both buffers
    for (int idx = t; idx < 2 * 96; idx += 256) {
        int c    = idx & 7;
        int side = (idx >> 3) & 1;
        int r    = (idx >> 4) % 6;
        int sb   = idx / 96;
        int pxs  = side ? 33 : 0;
        int sw   = (pxs & 7) << 2;
        int w    = (r * 34 + pxs) * 32 + ((c * 4) ^ sw);
        u32* dst = (u32*)(smraw + sb * SPLIT_BYTES);
        *(uint4*)(dst + w) = make_uint4(0, 0, 0, 0);
    }

    const uint2* wf2 = (const uint2*)wfrag;

    int m_lo = wid * 16 + gid;
    int m_hi = m_lo + 8;
    int row_lo = m_lo >> 5, x_lo = m_lo & 31;
    int row_hi = m_hi >> 5, x_hi = m_hi & 31;

    auto preload = [&](int itx, int sel) {
        const uint4* src = (const uint4*)in;
        u32 dbase = smem_base + (u32)sel * SPLIT_BYTES;
#pragma unroll
        for (int idx = t; idx < 1536; idx += 256) {
            int c  = idx & 7;
            int px = (idx >> 3) & 31;
            int r  = idx >> 8;
            const uint4* g = src + ((size_t)(n * 34 + itx * 4 + r) * 32 + px) * 8 + c;
            int sw = ((px + 1) & 7) << 2;
            int w  = (r * 34 + px + 1) * 32 + ((c * 4) ^ sw);
            cp16(dbase + (u32)w * 4, g);
        }
    };

    preload(0, 0);
    asm volatile("cp.async.commit_group;" ::: "memory");

#pragma unroll 1
    for (int it = 0; it < 8; it++) {
        if (it < 7) {
            preload(it + 1, (it + 1) & 1);
            asm volatile("cp.async.commit_group;" ::: "memory");
            asm volatile("cp.async.wait_group 1;" ::: "memory");
        } else {
            asm volatile("cp.async.wait_group 0;" ::: "memory");
        }
        __syncthreads();

        u32* slab = (u32*)(smraw + (it & 1) * SPLIT_BYTES);

        float acc[8][4];
#pragma unroll
        for (int nt = 0; nt < 8; nt++)
#pragma unroll
            for (int j = 0; j < 4; j++) acc[nt][j] = 0.f;

#pragma unroll 1
        for (int tap = 0; tap < 9; tap++) {
            int ky = tap / 3, kx = tap - ky * 3;
            int rl = row_lo + ky, pl = x_lo + kx;
            int rh = row_hi + ky, ph = x_hi + kx;
            int bl_ = (rl * 34 + pl) * 32, sl_ = (pl & 7) << 2;
            int bh_ = (rh * 34 + ph) * 32, sh_ = (ph & 7) << 2;
#pragma unroll
            for (int ks = 0; ks < 4; ks++) {
                int c0 = ks * 8 + ctg, c1 = ks * 8 + 4 + ctg;
                u32 a[4];
                a[0] = slab[bl_ + (c0 ^ sl_)];
                a[1] = slab[bh_ + (c0 ^ sh_)];
                a[2] = slab[bl_ + (c1 ^ sl_)];
                a[3] = slab[bh_ + (c1 ^ sh_)];

                const uint2* wh = wf2 + ((tap * 4 + ks) * 8) * 32 + lane;
#pragma unroll
                for (int nt = 0; nt < 8; nt++) {
                    uint2 bw = __ldg(wh + nt * 32);
                    mma16816(acc[nt], a, bw.x, bw.y);
                }
            }
        }

        int y0 = it * 4 + row_lo;
        int y1r = it * 4 + row_hi;
#pragma unroll
        for (int nt = 0; nt < 8; nt++) {
            int co = nt * 8 + ctg * 2;
            float v00 = fmaxf(acc[nt][0] + bias_s[co], 0.f);
            float v01 = fmaxf(acc[nt][1] + bias_s[co + 1], 0.f);
            float v10 = fmaxf(acc[nt][2] + bias_s[co], 0.f);
            float v11 = fmaxf(acc[nt][3] + bias_s[co + 1], 0.f);
            size_t a0 = (((size_t)n * 32 + y0) * 32 + x_lo) * 64 + co;
            size_t a1 = (((size_t)n * 32 + y1r) * 32 + x_hi) * 64 + co;
            *(u32*)&g_buf2[a0] = ph2(v00, v01);
            *(u32*)&g_buf2[a1] = ph2(v10, v11);
        }
        __syncthreads();
    }
}

// ============================================================
// Kernel E: 3x3 VALID conv, only the selected class channel.
// grid (5, N_BOX): 6 output rows per block, 8 input rows staged.
// ============================================================
#define OC_OFF_IN   2304
#define OC_OFF_RED  (2304 + 65536)
#define OC_SMEM_BYTES (2304 + 65536 + 1024)

__global__ __launch_bounds__(256) void outconv_kernel(
    const __half* __restrict__ buf2,
    const float* __restrict__ ow,    // [3][3][64][3]
    const float* __restrict__ ob,
    const int*   __restrict__ cls,
    float*       __restrict__ out)   // [N][30][30]
{
    extern __shared__ char ocsm[];
    float* ws   = (float*)ocsm;                 // [9][64]
    float* insm = (float*)(ocsm + OC_OFF_IN);   // [ci][8 rows][32 px]
    float (*red)[32] = (float(*)[32])(ocsm + OC_OFF_RED);

    int n   = blockIdx.y;
    int oy0 = blockIdx.x * 6;
    int t   = threadIdx.x;
    int k   = __ldg(&cls[n]);

    for (int i = t; i < 576; i += 256) ws[i] = ow[i * 3 + k];
    float bias = __ldg(&ob[k]);

    const uint4* b2 = (const uint4*)buf2;
    for (int idx = t; idx < 8 * 32 * 8; idx += 256) {
        int c  = idx & 7;
        int px = (idx >> 3) & 31;
        int ry = idx >> 8;
        uint4 v = b2[((size_t)(n * S + oy0 + ry) * S + px) * 8 + c];
        const __half2* hp = (const __half2*)&v;
#pragma unroll
        for (int j = 0; j < 4; j++) {
            float2 f = __half22float2(hp[j]);
            insm[(c * 8 + j * 2 + 0) * 256 + ry * 32 + px] = f.x;
            insm[(c * 8 + j * 2 + 1) * 256 + ry * 32 + px] = f.y;
        }
    }
    __syncthreads();

    int ox  = t & 31;
    int grp = t >> 5;

#pragma unroll 1
    for (int oyl = 0; oyl < 6; oyl++) {
        float part = 0.f;
        if (ox < OUTW) {
#pragma unroll
            for (int p = 0; p < 9; p++) {
                const int ky = p / 3, kx = p % 3;
#pragma unroll
                for (int ci = 0; ci < 8; ci++) {
                    int cig = grp * 8 + ci;
                    part += insm[cig * 256 + (oyl + ky) * 32 + ox + kx] * ws[p * 64 + cig];
                }
            }
        }
        red[grp][ox] = part;
        __syncthreads();
        if (grp == 0 && ox < OUTW) {
            float ssum = bias;
#pragma unroll
            for (int q = 0; q < 8; q++) ssum += red[q][ox];
            out[(size_t)n * (OUTW * OUTW) + (oy0 + oyl) * OUTW + ox] = ssum;
        }
        __syncthreads();
    }
}

// ============================================================
// Launch
// ============================================================
extern "C" void kernel_launch(void* const* d_in, const int* in_sizes, int n_in,
                              void* d_out, int out_size)
{
    const float* features = (const float*)d_in[0];
    const float* boxes    = (const float*)d_in[1];
    const int*   box_ids  = (const int*)d_in[2];
    const int*   cls      = (const int*)d_in[3];
    const float* w1       = (const float*)d_in[4];
    const float* b1       = (const float*)d_in[5];
    const float* w2       = (const float*)d_in[6];
    const float* b2       = (const float*)d_in[7];
    const float* ow       = (const float*)d_in[8];
    const float* ob       = (const float*)d_in[9];
    float* out = (float*)d_out;

    cudaFuncSetAttribute(conv1_kernel,
                         cudaFuncAttributeMaxDynamicSharedMemorySize, C1_SMEM_BYTES);
    cudaFuncSetAttribute(conv2_kernel,
                         cudaFuncAttributeMaxDynamicSharedMemorySize, C2_SMEM_BYTES);
    cudaFuncSetAttribute(outconv_kernel,
                         cudaFuncAttributeMaxDynamicSharedMemorySize, OC_SMEM_BYTES);

    void *s2, *wf, *p2;
    cudaGetSymbolAddress(&s2, g_s2);
    cudaGetSymbolAddress(&wf, g_wfrag);
    cudaGetSymbolAddress(&p2, g_buf2);

    zero_s2_guards<<<N_BOX, 256>>>();
    wprep_kernel<<<72, 256>>>(w1, w2);

    conv1_kernel<<<N_BOX, 256, C1_SMEM_BYTES>>>(
        features, boxes, box_ids, (const u32*)wf, b1);
    conv2_kernel<<<N_BOX, 256, C2_SMEM_BYTES>>>(
        (const __half*)s2, (const u32*)wf + 18432, b2);

    outconv_kernel<<<dim3(5, N_BOX), 256, OC_SMEM_BYTES>>>(
        (const __half*)p2, ow, ob, cls, out);
}

// round 12
// speedup vs baseline: 5.0994x; 1.1470x over previous
#include <cuda_runtime.h>
#include <cuda_fp16.h>
#include <cstddef>
#include <cstdint>

typedef unsigned long long u64;
typedef unsigned int u32;

#define N_BOX 1024
#define HF 192
#define CF 64
#define S 32
#define CH 64
#define OUTW 30

// =================== static scratch ===================
// g_s2: conv1 out, [box][34 rows][32 px][64 ch] fp16, rows 0/33 zero guards
__device__ __half g_s2[(size_t)N_BOX * 34 * 32 * 64];
__device__ __half g_buf2[(size_t)N_BOX * S * S * CH];   // conv2 out fp16
// B fragments (single fp16 weights) in mma.sync register order:
// [layer][tap][kstep][ntile][lane] x {b0,b1} u32
__device__ u32 g_wfrag[2 * 9 * 4 * 8 * 32 * 2];

__device__ __forceinline__ u32 ph2(float a, float b) {
    __half2 t = __floats2half2_rn(a, b);
    return *(u32*)&t;
}
__device__ __forceinline__ void mma16816(float* c, const u32* a, u32 b0, u32 b1) {
    asm volatile(
        "mma.sync.aligned.m16n8k16.row.col.f32.f16.f16.f32 "
        "{%0,%1,%2,%3}, {%4,%5,%6,%7}, {%8,%9}, {%0,%1,%2,%3};"
        : "+f"(c[0]), "+f"(c[1]), "+f"(c[2]), "+f"(c[3])
        : "r"(a[0]), "r"(a[1]), "r"(a[2]), "r"(a[3]), "r"(b0), "r"(b1));
}
__device__ __forceinline__ void cp16(u32 dst, const void* src) {
    asm volatile("cp.async.cg.shared.global [%0], [%1], 16;" :: "r"(dst), "l"(src));
}

// ============================================================
// Kernel B: weight prep -> mma B-fragment order, single fp16
// ============================================================
__global__ __launch_bounds__(256) void wprep_kernel(
    const float* __restrict__ w1, const float* __restrict__ w2)
{
    int i = blockIdx.x * 256 + threadIdx.x;
    if (i >= 18432) return;                  // 2 layers * 9 * 4 * 8 * 32
    int layer = i / 9216;
    int r     = i % 9216;
    int tap   = r / 1024;
    int r2    = r & 1023;
    int ks    = (r2 >> 8) & 3;
    int nt    = (r2 >> 5) & 7;
    int lane  = r2 & 31;
    int gid = lane >> 2, ctg = lane & 3;
    int ci0 = ks * 16 + ctg * 2;
    int co  = nt * 8 + gid;
    const float* W = layer ? w2 : w1;

    g_wfrag[i * 2]     = ph2(W[(tap * 64 + ci0) * 64 + co],
                             W[(tap * 64 + ci0 + 1) * 64 + co]);
    g_wfrag[i * 2 + 1] = ph2(W[(tap * 64 + ci0 + 8) * 64 + co],
                             W[(tap * 64 + ci0 + 9) * 64 + co]);
}

// ============================================================
// Kernel C: conv1 with FUSED crop_and_resize, single-pass fp16.
// CTA = one box, 256 threads (8 warps), 2 CTAs/SM.
// Per 4-row stage: bilinear-gather features -> fp16 slab in smem
// (double-buffered), then single-pass fp16 HMMA, epilogue -> g_s2 (rows +1).
// Also zeros its box's guard rows (0, 33) of g_s2.
// smem: 2 x slab 26112 + bias 256
// ============================================================
#define SPLIT_BYTES 26112
#define SLAB_WORDS  6528
#define C1_OFF_BIAS 52224
#define C1_SMEM_BYTES (52224 + 256)

__global__ __launch_bounds__(256, 2) void conv1_kernel(
    const float* __restrict__ feat,
    const float* __restrict__ boxes,
    const int*   __restrict__ box_ids,
    const u32*   __restrict__ wfrag,
    const float* __restrict__ bias)
{
    extern __shared__ char smraw[];
    float* bias_s = (float*)(smraw + C1_OFF_BIAS);

    int n   = blockIdx.x;
    int t   = threadIdx.x;
    int wid = t >> 5;
    int lane = t & 31;
    int gid = lane >> 2, ctg = lane & 3;

    if (t < 64) bias_s[t] = bias[t];

    // ---- zero this box's guard rows of g_s2 (rows 0 and 33)
    {
        uint4 z4 = make_uint4(0, 0, 0, 0);
        uint4* r0 = (uint4*)&g_s2[((size_t)n * 34 + 0) * 2048];
        uint4* r1 = (uint4*)&g_s2[((size_t)n * 34 + 33) * 2048];
        for (int i = t; i < 256; i += 256) { r0[i] = z4; r1[i] = z4; }
    }

    // box params
    float y1 = boxes[n * 4 + 0], x1 = boxes[n * 4 + 1];
    float y2 = boxes[n * 4 + 2], x2 = boxes[n * 4 + 3];
    int b = box_ids[n];
    const float4* f4 = (const float4*)(feat + (size_t)b * HF * HF * CF);

    // ---- zero x-guards (px_s = 0, 33) once, both buffers
    for (int idx = t; idx < 2 * 96; idx += 256) {
        int c    = idx & 7;
        int side = (idx >> 3) & 1;
        int r    = (idx >> 4) % 6;
        int sb   = idx / 96;
        int pxs  = side ? 33 : 0;
        int sw   = (pxs & 7) << 2;
        int w    = (r * 34 + pxs) * 32 + ((c * 4) ^ sw);
        u32* dst = (u32*)(smraw + sb * SPLIT_BYTES);
        *(uint4*)(dst + w) = make_uint4(0, 0, 0, 0);
    }

    const uint2* wf2 = (const uint2*)wfrag;

    // crop-thread mapping: px = t>>3 (0..31), cg = t&7 (2 chunks of 4 ch)
    int cpx = t >> 3;
    int cg  = t & 7;
    float xs  = (x1 + (float)cpx * (1.f / 31.f) * (x2 - x1)) * (float)(HF - 1);
    float x0f = fminf(fmaxf(floorf(xs), 0.f), (float)(HF - 1));
    float wx  = xs - x0f;
    int x0i = (int)x0f;
    int x1i = min(x0i + 1, HF - 1);
    int csw = ((cpx + 1) & 7) << 2;

    // MMA tile mapping
    int m_lo = wid * 16 + gid;
    int m_hi = m_lo + 8;
    int row_lo = m_lo >> 5, x_lo = m_lo & 31;
    int row_hi = m_hi >> 5, x_hi = m_hi & 31;

#pragma unroll 1
    for (int it = 0; it < 8; it++) {
        // ---- fused crop: fill stage `it` slab (buffer it&1), fp16 single
        {
            u32* shi = (u32*)(smraw + (it & 1) * SPLIT_BYTES);
#pragma unroll
            for (int r = 0; r < 6; r++) {
                int j  = it * 4 + r;                      // 0..33
                float wz = (j == 0 || j == 33) ? 0.f : 1.f;
                int y  = min(max(j - 1, 0), S - 1);
                float ys  = (y1 + (float)y * (1.f / 31.f) * (y2 - y1)) * (float)(HF - 1);
                float y0f = fminf(fmaxf(floorf(ys), 0.f), (float)(HF - 1));
                float wy  = ys - y0f;
                int y0i = (int)y0f;
                int y1i = min(y0i + 1, HF - 1);
                const float4* r0 = f4 + (size_t)y0i * HF * 16;
                const float4* r1 = f4 + (size_t)y1i * HF * 16;
                int base = (r * 34 + cpx + 1) * 32;
                float omx = 1.f - wx, omy = 1.f - wy;
#pragma unroll
                for (int q = 0; q < 2; q++) {
                    int ck = cg * 2 + q;                  // 4-channel chunk
                    float4 v00 = r0[x0i * 16 + ck];
                    float4 v01 = r0[x1i * 16 + ck];
                    float4 v10 = r1[x0i * 16 + ck];
                    float4 v11 = r1[x1i * 16 + ck];
                    float o0 = ((v00.x * omx + v01.x * wx) * omy + (v10.x * omx + v11.x * wx) * wy) * wz;
                    float o1 = ((v00.y * omx + v01.y * wx) * omy + (v10.y * omx + v11.y * wx) * wy) * wz;
                    float o2 = ((v00.z * omx + v01.z * wx) * omy + (v10.z * omx + v11.z * wx) * wy) * wz;
                    float o3 = ((v00.w * omx + v01.w * wx) * omy + (v10.w * omx + v11.w * wx) * wy) * wz;
                    int w = base + ((ck * 2) ^ csw);
                    uint2 Hh;
                    Hh.x = ph2(o0, o1);
                    Hh.y = ph2(o2, o3);
                    *(uint2*)(shi + w) = Hh;
                }
            }
        }
        __syncthreads();   // slab `it` complete; prev iter's other buffer free

        u32* slab = (u32*)(smraw + (it & 1) * SPLIT_BYTES);

        float acc[8][4];
#pragma unroll
        for (int nt = 0; nt < 8; nt++)
#pragma unroll
            for (int j = 0; j < 4; j++) acc[nt][j] = 0.f;

#pragma unroll 1
        for (int tap = 0; tap < 9; tap++) {
            int ky = tap / 3, kx = tap - ky * 3;
            int rl = row_lo + ky, pl = x_lo + kx;
            int rh = row_hi + ky, ph = x_hi + kx;
            int bl_ = (rl * 34 + pl) * 32, sl_ = (pl & 7) << 2;
            int bh_ = (rh * 34 + ph) * 32, sh_ = (ph & 7) << 2;
#pragma unroll
            for (int ks = 0; ks < 4; ks++) {
                int c0 = ks * 8 + ctg, c1 = ks * 8 + 4 + ctg;
                u32 a[4];
                a[0] = slab[bl_ + (c0 ^ sl_)];
                a[1] = slab[bh_ + (c0 ^ sh_)];
                a[2] = slab[bl_ + (c1 ^ sl_)];
                a[3] = slab[bh_ + (c1 ^ sh_)];

                const uint2* wh = wf2 + ((tap * 4 + ks) * 8) * 32 + lane;
#pragma unroll
                for (int nt = 0; nt < 8; nt++) {
                    uint2 bw = __ldg(wh + nt * 32);
                    mma16816(acc[nt], a, bw.x, bw.y);
                }
            }
        }

        // ---- epilogue: bias + ReLU, single-fp16 write to g_s2 (rows +1)
        int y0 = it * 4 + row_lo;
        int y1r = it * 4 + row_hi;
#pragma unroll
        for (int nt = 0; nt < 8; nt++) {
            int co = nt * 8 + ctg * 2;
            float v00 = fmaxf(acc[nt][0] + bias_s[co], 0.f);
            float v01 = fmaxf(acc[nt][1] + bias_s[co + 1], 0.f);
            float v10 = fmaxf(acc[nt][2] + bias_s[co], 0.f);
            float v11 = fmaxf(acc[nt][3] + bias_s[co + 1], 0.f);
            size_t a0 = (((size_t)n * 34 + y0 + 1) * 32 + x_lo) * 64 + co;
            size_t a1 = (((size_t)n * 34 + y1r + 1) * 32 + x_hi) * 64 + co;
            *(u32*)&g_s2[a0] = ph2(v00, v01);
            *(u32*)&g_s2[a1] = ph2(v10, v11);
        }
        // no second sync: double buffer, next crop targets the other buffer
    }
}

// ============================================================
// Kernel D: conv2, single-pass fp16 HMMA.
// cp.async double-buffered slab. 2 CTAs/SM.
// ============================================================
#define C2_OFF_BIAS 52224
#define C2_SMEM_BYTES (52224 + 256)

__global__ __launch_bounds__(256, 2) void conv2_kernel(
    const __half* __restrict__ in,        // g_s2
    const u32*    __restrict__ wfrag,     // layer-1 fragment array
    const float*  __restrict__ bias)
{
    extern __shared__ char smraw[];
    float* bias_s = (float*)(smraw + C2_OFF_BIAS);
    u32 smem_base = (u32)__cvta_generic_to_shared(smraw);

    int n   = blockIdx.x;
    int t   = threadIdx.x;
    int wid = t >> 5;
    int lane = t & 31;
    int gid = lane >> 2, ctg = lane & 3;

    if (t < 64) bias_s[t] = bias[t];

    // zero x-guards for both buffers
    for (int idx = t; idx < 2 * 96; idx += 256) {
        int c    = idx & 7;
        int side = (idx >> 3) & 1;
        int r    = (idx >> 4) % 6;
        int sb   = idx / 96;
        int pxs  = side ? 33 : 0;
        int sw   = (pxs & 7) << 2;
        int w    = (r * 34 + pxs) * 32 + ((c * 4) ^ sw);
        u32* dst = (u32*)(smraw + sb * SPLIT_BYTES);
        *(uint4*)(dst + w) = make_uint4(0, 0, 0, 0);
    }

    const uint2* wf2 = (const uint2*)wfrag;

    int m_lo = wid * 16 + gid;
    int m_hi = m_lo + 8;
    int row_lo = m_lo >> 5, x_lo = m_lo & 31;
    int row_hi = m_hi >> 5, x_hi = m_hi & 31;

    auto preload = [&](int itx, int sel) {
        const uint4* src = (const uint4*)in;
        u32 dbase = smem_base + (u32)sel * SPLIT_BYTES;
#pragma unroll
        for (int idx = t; idx < 1536; idx += 256) {
            int c  = idx & 7;
            int px = (idx >> 3) & 31;
            int r  = idx >> 8;
            const uint4* g = src + ((size_t)(n * 34 + itx * 4 + r) * 32 + px) * 8 + c;
            int sw = ((px + 1) & 7) << 2;
            int w  = (r * 34 + px + 1) * 32 + ((c * 4) ^ sw);
            cp16(dbase + (u32)w * 4, g);
        }
    };

    preload(0, 0);
    asm volatile("cp.async.commit_group;" ::: "memory");

#pragma unroll 1
    for (int it = 0; it < 8; it++) {
        if (it < 7) {
            preload(it + 1, (it + 1) & 1);
            asm volatile("cp.async.commit_group;" ::: "memory");
            asm volatile("cp.async.wait_group 1;" ::: "memory");
        } else {
            asm volatile("cp.async.wait_group 0;" ::: "memory");
        }
        __syncthreads();

        u32* slab = (u32*)(smraw + (it & 1) * SPLIT_BYTES);

        float acc[8][4];
#pragma unroll
        for (int nt = 0; nt < 8; nt++)
#pragma unroll
            for (int j = 0; j < 4; j++) acc[nt][j] = 0.f;

#pragma unroll 1
        for (int tap = 0; tap < 9; tap++) {
            int ky = tap / 3, kx = tap - ky * 3;
            int rl = row_lo + ky, pl = x_lo + kx;
            int rh = row_hi + ky, ph = x_hi + kx;
            int bl_ = (rl * 34 + pl) * 32, sl_ = (pl & 7) << 2;
            int bh_ = (rh * 34 + ph) * 32, sh_ = (ph & 7) << 2;
#pragma unroll
            for (int ks = 0; ks < 4; ks++) {
                int c0 = ks * 8 + ctg, c1 = ks * 8 + 4 + ctg;
                u32 a[4];
                a[0] = slab[bl_ + (c0 ^ sl_)];
                a[1] = slab[bh_ + (c0 ^ sh_)];
                a[2] = slab[bl_ + (c1 ^ sl_)];
                a[3] = slab[bh_ + (c1 ^ sh_)];

                const uint2* wh = wf2 + ((tap * 4 + ks) * 8) * 32 + lane;
#pragma unroll
                for (int nt = 0; nt < 8; nt++) {
                    uint2 bw = __ldg(wh + nt * 32);
                    mma16816(acc[nt], a, bw.x, bw.y);
                }
            }
        }

        int y0 = it * 4 + row_lo;
        int y1r = it * 4 + row_hi;
#pragma unroll
        for (int nt = 0; nt < 8; nt++) {
            int co = nt * 8 + ctg * 2;
            float v00 = fmaxf(acc[nt][0] + bias_s[co], 0.f);
            float v01 = fmaxf(acc[nt][1] + bias_s[co + 1], 0.f);
            float v10 = fmaxf(acc[nt][2] + bias_s[co], 0.f);
            float v11 = fmaxf(acc[nt][3] + bias_s[co + 1], 0.f);
            size_t a0 = (((size_t)n * 32 + y0) * 32 + x_lo) * 64 + co;
            size_t a1 = (((size_t)n * 32 + y1r) * 32 + x_hi) * 64 + co;
            *(u32*)&g_buf2[a0] = ph2(v00, v01);
            *(u32*)&g_buf2[a1] = ph2(v10, v11);
        }
        __syncthreads();
    }
}

// ============================================================
// Kernel E: 3x3 VALID conv, only the selected class channel.
// grid (5, N_BOX): 6 output rows per block, 8 input rows staged.
// ============================================================
#define OC_OFF_IN   2304
#define OC_OFF_RED  (2304 + 65536)
#define OC_SMEM_BYTES (2304 + 65536 + 1024)

__global__ __launch_bounds__(256) void outconv_kernel(
    const __half* __restrict__ buf2,
    const float* __restrict__ ow,    // [3][3][64][3]
    const float* __restrict__ ob,
    const int*   __restrict__ cls,
    float*       __restrict__ out)   // [N][30][30]
{
    extern __shared__ char ocsm[];
    float* ws   = (float*)ocsm;                 // [9][64]
    float* insm = (float*)(ocsm + OC_OFF_IN);   // [ci][8 rows][32 px]
    float (*red)[32] = (float(*)[32])(ocsm + OC_OFF_RED);

    int n   = blockIdx.y;
    int oy0 = blockIdx.x * 6;
    int t   = threadIdx.x;
    int k   = __ldg(&cls[n]);

    for (int i = t; i < 576; i += 256) ws[i] = ow[i * 3 + k];
    float bias = __ldg(&ob[k]);

    const uint4* b2 = (const uint4*)buf2;
    for (int idx = t; idx < 8 * 32 * 8; idx += 256) {
        int c  = idx & 7;
        int px = (idx >> 3) & 31;
        int ry = idx >> 8;
        uint4 v = b2[((size_t)(n * S + oy0 + ry) * S + px) * 8 + c];
        const __half2* hp = (const __half2*)&v;
#pragma unroll
        for (int j = 0; j < 4; j++) {
            float2 f = __half22float2(hp[j]);
            insm[(c * 8 + j * 2 + 0) * 256 + ry * 32 + px] = f.x;
            insm[(c * 8 + j * 2 + 1) * 256 + ry * 32 + px] = f.y;
        }
    }
    __syncthreads();

    int ox  = t & 31;
    int grp = t >> 5;

#pragma unroll 1
    for (int oyl = 0; oyl < 6; oyl++) {
        float part = 0.f;
        if (ox < OUTW) {
#pragma unroll
            for (int p = 0; p < 9; p++) {
                const int ky = p / 3, kx = p % 3;
#pragma unroll
                for (int ci = 0; ci < 8; ci++) {
                    int cig = grp * 8 + ci;
                    part += insm[cig * 256 + (oyl + ky) * 32 + ox + kx] * ws[p * 64 + cig];
                }
            }
        }
        red[grp][ox] = part;
        __syncthreads();
        if (grp == 0 && ox < OUTW) {
            float ssum = bias;
#pragma unroll
            for (int q = 0; q < 8; q++) ssum += red[q][ox];
            out[(size_t)n * (OUTW * OUTW) + (oy0 + oyl) * OUTW + ox] = ssum;
        }
        __syncthreads();
    }
}

// ============================================================
// Launch
// ============================================================
extern "C" void kernel_launch(void* const* d_in, const int* in_sizes, int n_in,
                              void* d_out, int out_size)
{
    const float* features = (const float*)d_in[0];
    const float* boxes    = (const float*)d_in[1];
    const int*   box_ids  = (const int*)d_in[2];
    const int*   cls      = (const int*)d_in[3];
    const float* w1       = (const float*)d_in[4];
    const float* b1       = (const float*)d_in[5];
    const float* w2       = (const float*)d_in[6];
    const float* b2       = (const float*)d_in[7];
    const float* ow       = (const float*)d_in[8];
    const float* ob       = (const float*)d_in[9];
    float* out = (float*)d_out;

    cudaFuncSetAttribute(conv1_kernel,
                         cudaFuncAttributeMaxDynamicSharedMemorySize, C1_SMEM_BYTES);
    cudaFuncSetAttribute(conv2_kernel,
                         cudaFuncAttributeMaxDynamicSharedMemorySize, C2_SMEM_BYTES);
    cudaFuncSetAttribute(outconv_kernel,
                         cudaFuncAttributeMaxDynamicSharedMemorySize, OC_SMEM_BYTES);

    void *s2, *wf, *p2;
    cudaGetSymbolAddress(&s2, g_s2);
    cudaGetSymbolAddress(&wf, g_wfrag);
    cudaGetSymbolAddress(&p2, g_buf2);

    wprep_kernel<<<72, 256>>>(w1, w2);

    conv1_kernel<<<N_BOX, 256, C1_SMEM_BYTES>>>(
        features, boxes, box_ids, (const u32*)wf, b1);
    conv2_kernel<<<N_BOX, 256, C2_SMEM_BYTES>>>(
        (const __half*)s2, (const u32*)wf + 18432, b2);

    outconv_kernel<<<dim3(5, N_BOX), 256, OC_SMEM_BYTES>>>(
        (const __half*)p2, ow, ob, cls, out);
}

// round 13
// speedup vs baseline: 5.1431x; 1.0086x over previous
#include <cuda_runtime.h>
#include <cuda_fp16.h>
#include <cstddef>
#include <cstdint>

typedef unsigned long long u64;
typedef unsigned int u32;

#define N_BOX 1024
#define HF 192
#define CF 64
#define S 32
#define CH 64
#define OUTW 30

// =================== static scratch ===================
// g_s2: conv1 out, [box][34 rows][32 px][64 ch] fp16, rows 0/33 zero guards
__device__ __half g_s2[(size_t)N_BOX * 34 * 32 * 64];
__device__ __half g_buf2[(size_t)N_BOX * S * S * CH];   // conv2 out fp16
// B fragments (single fp16 weights) in mma.sync register order:
// [layer][tap][kstep][ntile][lane] x {b0,b1} u32
__device__ u32 g_wfrag[2 * 9 * 4 * 8 * 32 * 2];

__device__ __forceinline__ u32 ph2(float a, float b) {
    __half2 t = __floats2half2_rn(a, b);
    return *(u32*)&t;
}
__device__ __forceinline__ void mma16816(float* c, const u32* a, u32 b0, u32 b1) {
    asm volatile(
        "mma.sync.aligned.m16n8k16.row.col.f32.f16.f16.f32 "
        "{%0,%1,%2,%3}, {%4,%5,%6,%7}, {%8,%9}, {%0,%1,%2,%3};"
        : "+f"(c[0]), "+f"(c[1]), "+f"(c[2]), "+f"(c[3])
        : "r"(a[0]), "r"(a[1]), "r"(a[2]), "r"(a[3]), "r"(b0), "r"(b1));
}
__device__ __forceinline__ void cp16(u32 dst, const void* src) {
    asm volatile("cp.async.cg.shared.global [%0], [%1], 16;" :: "r"(dst), "l"(src));
}

// ============================================================
// Kernel B: weight prep -> mma B-fragment order, single fp16
// ============================================================
__global__ __launch_bounds__(256) void wprep_kernel(
    const float* __restrict__ w1, const float* __restrict__ w2)
{
    int i = blockIdx.x * 256 + threadIdx.x;
    if (i >= 18432) return;                  // 2 layers * 9 * 4 * 8 * 32
    int layer = i / 9216;
    int r     = i % 9216;
    int tap   = r / 1024;
    int r2    = r & 1023;
    int ks    = (r2 >> 8) & 3;
    int nt    = (r2 >> 5) & 7;
    int lane  = r2 & 31;
    int gid = lane >> 2, ctg = lane & 3;
    int ci0 = ks * 16 + ctg * 2;
    int co  = nt * 8 + gid;
    const float* W = layer ? w2 : w1;

    g_wfrag[i * 2]     = ph2(W[(tap * 64 + ci0) * 64 + co],
                             W[(tap * 64 + ci0 + 1) * 64 + co]);
    g_wfrag[i * 2 + 1] = ph2(W[(tap * 64 + ci0 + 8) * 64 + co],
                             W[(tap * 64 + ci0 + 9) * 64 + co]);
}

// ============================================================
// Kernel C: conv1 with FUSED crop_and_resize, single-pass fp16.
// CTA = one box, 256 threads (8 warps), 2 CTAs/SM.
// ============================================================
#define SPLIT_BYTES 26112
#define SLAB_WORDS  6528
#define C1_OFF_BIAS 52224
#define C1_SMEM_BYTES (52224 + 256)

__global__ __launch_bounds__(256, 2) void conv1_kernel(
    const float* __restrict__ feat,
    const float* __restrict__ boxes,
    const int*   __restrict__ box_ids,
    const u32*   __restrict__ wfrag,
    const float* __restrict__ bias)
{
    extern __shared__ char smraw[];
    float* bias_s = (float*)(smraw + C1_OFF_BIAS);

    int n   = blockIdx.x;
    int t   = threadIdx.x;
    int wid = t >> 5;
    int lane = t & 31;
    int gid = lane >> 2, ctg = lane & 3;

    if (t < 64) bias_s[t] = bias[t];

    // ---- zero this box's guard rows of g_s2 (rows 0 and 33)
    {
        uint4 z4 = make_uint4(0, 0, 0, 0);
        uint4* r0 = (uint4*)&g_s2[((size_t)n * 34 + 0) * 2048];
        uint4* r1 = (uint4*)&g_s2[((size_t)n * 34 + 33) * 2048];
        for (int i = t; i < 256; i += 256) { r0[i] = z4; r1[i] = z4; }
    }

    // box params
    float y1 = boxes[n * 4 + 0], x1 = boxes[n * 4 + 1];
    float y2 = boxes[n * 4 + 2], x2 = boxes[n * 4 + 3];
    int b = box_ids[n];
    const float4* f4 = (const float4*)(feat + (size_t)b * HF * HF * CF);

    // ---- zero x-guards (px_s = 0, 33) once, both buffers
    for (int idx = t; idx < 2 * 96; idx += 256) {
        int c    = idx & 7;
        int side = (idx >> 3) & 1;
        int r    = (idx >> 4) % 6;
        int sb   = idx / 96;
        int pxs  = side ? 33 : 0;
        int sw   = (pxs & 7) << 2;
        int w    = (r * 34 + pxs) * 32 + ((c * 4) ^ sw);
        u32* dst = (u32*)(smraw + sb * SPLIT_BYTES);
        *(uint4*)(dst + w) = make_uint4(0, 0, 0, 0);
    }

    const uint2* wf2 = (const uint2*)wfrag;

    // crop-thread mapping: px = t>>3 (0..31), cg = t&7 (2 chunks of 4 ch)
    int cpx = t >> 3;
    int cg  = t & 7;
    float xs  = (x1 + (float)cpx * (1.f / 31.f) * (x2 - x1)) * (float)(HF - 1);
    float x0f = fminf(fmaxf(floorf(xs), 0.f), (float)(HF - 1));
    float wx  = xs - x0f;
    int x0i = (int)x0f;
    int x1i = min(x0i + 1, HF - 1);
    int csw = ((cpx + 1) & 7) << 2;

    // MMA tile mapping
    int m_lo = wid * 16 + gid;
    int m_hi = m_lo + 8;
    int row_lo = m_lo >> 5, x_lo = m_lo & 31;
    int row_hi = m_hi >> 5, x_hi = m_hi & 31;

#pragma unroll 1
    for (int it = 0; it < 8; it++) {
        // ---- fused crop: fill stage `it` slab (buffer it&1), fp16 single
        {
            u32* shi = (u32*)(smraw + (it & 1) * SPLIT_BYTES);
#pragma unroll
            for (int r = 0; r < 6; r++) {
                int j  = it * 4 + r;                      // 0..33
                float wz = (j == 0 || j == 33) ? 0.f : 1.f;
                int y  = min(max(j - 1, 0), S - 1);
                float ys  = (y1 + (float)y * (1.f / 31.f) * (y2 - y1)) * (float)(HF - 1);
                float y0f = fminf(fmaxf(floorf(ys), 0.f), (float)(HF - 1));
                float wy  = ys - y0f;
                int y0i = (int)y0f;
                int y1i = min(y0i + 1, HF - 1);
                const float4* r0 = f4 + (size_t)y0i * HF * 16;
                const float4* r1 = f4 + (size_t)y1i * HF * 16;
                int base = (r * 34 + cpx + 1) * 32;
                float omx = 1.f - wx, omy = 1.f - wy;
#pragma unroll
                for (int q = 0; q < 2; q++) {
                    int ck = cg * 2 + q;                  // 4-channel chunk
                    float4 v00 = r0[x0i * 16 + ck];
                    float4 v01 = r0[x1i * 16 + ck];
                    float4 v10 = r1[x0i * 16 + ck];
                    float4 v11 = r1[x1i * 16 + ck];
                    float o0 = ((v00.x * omx + v01.x * wx) * omy + (v10.x * omx + v11.x * wx) * wy) * wz;
                    float o1 = ((v00.y * omx + v01.y * wx) * omy + (v10.y * omx + v11.y * wx) * wy) * wz;
                    float o2 = ((v00.z * omx + v01.z * wx) * omy + (v10.z * omx + v11.z * wx) * wy) * wz;
                    float o3 = ((v00.w * omx + v01.w * wx) * omy + (v10.w * omx + v11.w * wx) * wy) * wz;
                    int w = base + ((ck * 2) ^ csw);
                    uint2 Hh;
                    Hh.x = ph2(o0, o1);
                    Hh.y = ph2(o2, o3);
                    *(uint2*)(shi + w) = Hh;
                }
            }
        }
        __syncthreads();   // slab `it` complete; prev iter's other buffer free

        u32* slab = (u32*)(smraw + (it & 1) * SPLIT_BYTES);

        float acc[8][4];
#pragma unroll
        for (int nt = 0; nt < 8; nt++)
#pragma unroll
            for (int j = 0; j < 4; j++) acc[nt][j] = 0.f;

#pragma unroll 1
        for (int tap = 0; tap < 9; tap++) {
            int ky = tap / 3, kx = tap - ky * 3;
            int rl = row_lo + ky, pl = x_lo + kx;
            int rh = row_hi + ky, ph = x_hi + kx;
            int bl_ = (rl * 34 + pl) * 32, sl_ = (pl & 7) << 2;
            int bh_ = (rh * 34 + ph) * 32, sh_ = (ph & 7) << 2;
#pragma unroll
            for (int ks = 0; ks < 4; ks++) {
                int c0 = ks * 8 + ctg, c1 = ks * 8 + 4 + ctg;
                u32 a[4];
                a[0] = slab[bl_ + (c0 ^ sl_)];
                a[1] = slab[bh_ + (c0 ^ sh_)];
                a[2] = slab[bl_ + (c1 ^ sl_)];
                a[3] = slab[bh_ + (c1 ^ sh_)];

                const uint2* wh = wf2 + ((tap * 4 + ks) * 8) * 32 + lane;
#pragma unroll
                for (int nt = 0; nt < 8; nt++) {
                    uint2 bw = __ldg(wh + nt * 32);
                    mma16816(acc[nt], a, bw.x, bw.y);
                }
            }
        }

        // ---- epilogue: bias + ReLU, single-fp16 write to g_s2 (rows +1)
        int y0 = it * 4 + row_lo;
        int y1r = it * 4 + row_hi;
#pragma unroll
        for (int nt = 0; nt < 8; nt++) {
            int co = nt * 8 + ctg * 2;
            float v00 = fmaxf(acc[nt][0] + bias_s[co], 0.f);
            float v01 = fmaxf(acc[nt][1] + bias_s[co + 1], 0.f);
            float v10 = fmaxf(acc[nt][2] + bias_s[co], 0.f);
            float v11 = fmaxf(acc[nt][3] + bias_s[co + 1], 0.f);
            size_t a0 = (((size_t)n * 34 + y0 + 1) * 32 + x_lo) * 64 + co;
            size_t a1 = (((size_t)n * 34 + y1r + 1) * 32 + x_hi) * 64 + co;
            *(u32*)&g_s2[a0] = ph2(v00, v01);
            *(u32*)&g_s2[a1] = ph2(v10, v11);
        }
        // no second sync: double buffer, next crop targets the other buffer
    }
}

// ============================================================
// Kernel D: conv2, single-pass fp16 HMMA.
// cp.async double-buffered slab. 2 CTAs/SM.
// ============================================================
#define C2_OFF_BIAS 52224
#define C2_SMEM_BYTES (52224 + 256)

__global__ __launch_bounds__(256, 2) void conv2_kernel(
    const __half* __restrict__ in,        // g_s2
    const u32*    __restrict__ wfrag,     // layer-1 fragment array
    const float*  __restrict__ bias)
{
    extern __shared__ char smraw[];
    float* bias_s = (float*)(smraw + C2_OFF_BIAS);
    u32 smem_base = (u32)__cvta_generic_to_shared(smraw);

    int n   = blockIdx.x;
    int t   = threadIdx.x;
    int wid = t >> 5;
    int lane = t & 31;
    int gid = lane >> 2, ctg = lane & 3;

    if (t < 64) bias_s[t] = bias[t];

    // zero x-guards for both buffers
    for (int idx = t; idx < 2 * 96; idx += 256) {
        int c    = idx & 7;
        int side = (idx >> 3) & 1;
        int r    = (idx >> 4) % 6;
        int sb   = idx / 96;
        int pxs  = side ? 33 : 0;
        int sw   = (pxs & 7) << 2;
        int w    = (r * 34 + pxs) * 32 + ((c * 4) ^ sw);
        u32* dst = (u32*)(smraw + sb * SPLIT_BYTES);
        *(uint4*)(dst + w) = make_uint4(0, 0, 0, 0);
    }

    const uint2* wf2 = (const uint2*)wfrag;

    int m_lo = wid * 16 + gid;
    int m_hi = m_lo + 8;
    int row_lo = m_lo >> 5, x_lo = m_lo & 31;
    int row_hi = m_hi >> 5, x_hi = m_hi & 31;

    auto preload = [&](int itx, int sel) {
        const uint4* src = (const uint4*)in;
        u32 dbase = smem_base + (u32)sel * SPLIT_BYTES;
#pragma unroll
        for (int idx = t; idx < 1536; idx += 256) {
            int c  = idx & 7;
            int px = (idx >> 3) & 31;
            int r  = idx >> 8;
            const uint4* g = src + ((size_t)(n * 34 + itx * 4 + r) * 32 + px) * 8 + c;
            int sw = ((px + 1) & 7) << 2;
            int w  = (r * 34 + px + 1) * 32 + ((c * 4) ^ sw);
            cp16(dbase + (u32)w * 4, g);
        }
    };

    preload(0, 0);
    asm volatile("cp.async.commit_group;" ::: "memory");

#pragma unroll 1
    for (int it = 0; it < 8; it++) {
        if (it < 7) {
            preload(it + 1, (it + 1) & 1);
            asm volatile("cp.async.commit_group;" ::: "memory");
            asm volatile("cp.async.wait_group 1;" ::: "memory");
        } else {
            asm volatile("cp.async.wait_group 0;" ::: "memory");
        }
        __syncthreads();

        u32* slab = (u32*)(smraw + (it & 1) * SPLIT_BYTES);

        float acc[8][4];
#pragma unroll
        for (int nt = 0; nt < 8; nt++)
#pragma unroll
            for (int j = 0; j < 4; j++) acc[nt][j] = 0.f;

#pragma unroll 1
        for (int tap = 0; tap < 9; tap++) {
            int ky = tap / 3, kx = tap - ky * 3;
            int rl = row_lo + ky, pl = x_lo + kx;
            int rh = row_hi + ky, ph = x_hi + kx;
            int bl_ = (rl * 34 + pl) * 32, sl_ = (pl & 7) << 2;
            int bh_ = (rh * 34 + ph) * 32, sh_ = (ph & 7) << 2;
#pragma unroll
            for (int ks = 0; ks < 4; ks++) {
                int c0 = ks * 8 + ctg, c1 = ks * 8 + 4 + ctg;
                u32 a[4];
                a[0] = slab[bl_ + (c0 ^ sl_)];
                a[1] = slab[bh_ + (c0 ^ sh_)];
                a[2] = slab[bl_ + (c1 ^ sl_)];
                a[3] = slab[bh_ + (c1 ^ sh_)];

                const uint2* wh = wf2 + ((tap * 4 + ks) * 8) * 32 + lane;
#pragma unroll
                for (int nt = 0; nt < 8; nt++) {
                    uint2 bw = __ldg(wh + nt * 32);
                    mma16816(acc[nt], a, bw.x, bw.y);
                }
            }
        }

        int y0 = it * 4 + row_lo;
        int y1r = it * 4 + row_hi;
#pragma unroll
        for (int nt = 0; nt < 8; nt++) {
            int co = nt * 8 + ctg * 2;
            float v00 = fmaxf(acc[nt][0] + bias_s[co], 0.f);
            float v01 = fmaxf(acc[nt][1] + bias_s[co + 1], 0.f);
            float v10 = fmaxf(acc[nt][2] + bias_s[co], 0.f);
            float v11 = fmaxf(acc[nt][3] + bias_s[co + 1], 0.f);
            size_t a0 = (((size_t)n * 32 + y0) * 32 + x_lo) * 64 + co;
            size_t a1 = (((size_t)n * 32 + y1r) * 32 + x_hi) * 64 + co;
            *(u32*)&g_buf2[a0] = ph2(v00, v01);
            *(u32*)&g_buf2[a1] = ph2(v10, v11);
        }
        __syncthreads();
    }
}

// ============================================================
// Kernel E: 3x3 VALID conv, selected class only.
// grid (4, N_BOX): block computes 8 output rows (last block 6),
// ONE OUTPUT PER THREAD, no syncs in compute loop.
// smem: insm fp32 [64 ci][stride 337] (10 rows x 32 px region) + ws[9][64]
// ============================================================
#define OC_STRIDE   337
#define OC_WS_OFF   (64 * OC_STRIDE * 4)              // 86272
#define OC_SMEM_BYTES (OC_WS_OFF + 2304 + 64)

__global__ __launch_bounds__(256, 2) void outconv_kernel(
    const __half* __restrict__ buf2,
    const float* __restrict__ ow,    // [3][3][64][3]
    const float* __restrict__ ob,
    const int*   __restrict__ cls,
    float*       __restrict__ out)   // [N][30][30]
{
    extern __shared__ char ocsm[];
    float* insm = (float*)ocsm;                  // [ci][337] region
    float* ws   = (float*)(ocsm + OC_WS_OFF);    // [9][64]

    int n    = blockIdx.y;
    int bx   = blockIdx.x;
    int oy0  = bx * 8;
    int nrow = (bx == 3) ? 6 : 8;                // output rows this block
    int nin  = nrow + 2;                         // input rows staged
    int t    = threadIdx.x;
    int k    = __ldg(&cls[n]);

    for (int i = t; i < 576; i += 256) ws[i] = ow[i * 3 + k];
    float bias = __ldg(&ob[k]);

    // stage input rows oy0..oy0+nin-1, fp16 -> fp32, transposed [ci][ry*32+px]
    const uint4* b2 = (const uint4*)buf2;
    for (int idx = t; idx < nin * 32 * 8; idx += 256) {
        int c  = idx & 7;                        // 8-channel chunk
        int px = (idx >> 3) & 31;
        int ry = idx >> 8;
        uint4 v = b2[((size_t)(n * S + oy0 + ry) * S + px) * 8 + c];
        const __half2* hp = (const __half2*)&v;
#pragma unroll
        for (int j = 0; j < 4; j++) {
            float2 f = __half22float2(hp[j]);
            insm[(c * 8 + j * 2 + 0) * OC_STRIDE + ry * 32 + px] = f.x;
            insm[(c * 8 + j * 2 + 1) * OC_STRIDE + ry * 32 + px] = f.y;
        }
    }
    __syncthreads();

    int p = t;
    if (p < nrow * OUTW) {
        int oyl = p / OUTW;
        int ox  = p - oyl * OUTW;
        float acc = bias;
#pragma unroll 1
        for (int tap = 0; tap < 9; tap++) {
            int ky = tap / 3, kx = tap - ky * 3;
            const float* ip = insm + (oyl + ky) * 32 + ox + kx;
            const float* wp = ws + tap * 64;
#pragma unroll
            for (int ci = 0; ci < 64; ci++)
                acc += ip[ci * OC_STRIDE] * wp[ci];
        }
        out[(size_t)n * (OUTW * OUTW) + (oy0 + oyl) * OUTW + ox] = acc;
    }
}

// ============================================================
// Launch
// ============================================================
extern "C" void kernel_launch(void* const* d_in, const int* in_sizes, int n_in,
                              void* d_out, int out_size)
{
    const float* features = (const float*)d_in[0];
    const float* boxes    = (const float*)d_in[1];
    const int*   box_ids  = (const int*)d_in[2];
    const int*   cls      = (const int*)d_in[3];
    const float* w1       = (const float*)d_in[4];
    const float* b1       = (const float*)d_in[5];
    const float* w2       = (const float*)d_in[6];
    const float* b2       = (const float*)d_in[7];
    const float* ow       = (const float*)d_in[8];
    const float* ob       = (const float*)d_in[9];
    float* out = (float*)d_out;

    cudaFuncSetAttribute(conv1_kernel,
                         cudaFuncAttributeMaxDynamicSharedMemorySize, C1_SMEM_BYTES);
    cudaFuncSetAttribute(conv2_kernel,
                         cudaFuncAttributeMaxDynamicSharedMemorySize, C2_SMEM_BYTES);
    cudaFuncSetAttribute(outconv_kernel,
                         cudaFuncAttributeMaxDynamicSharedMemorySize, OC_SMEM_BYTES);

    void *s2, *wf, *p2;
    cudaGetSymbolAddress(&s2, g_s2);
    cudaGetSymbolAddress(&wf, g_wfrag);
    cudaGetSymbolAddress(&p2, g_buf2);

    wprep_kernel<<<72, 256>>>(w1, w2);

    conv1_kernel<<<N_BOX, 256, C1_SMEM_BYTES>>>(
        features, boxes, box_ids, (const u32*)wf, b1);
    conv2_kernel<<<N_BOX, 256, C2_SMEM_BYTES>>>(
        (const __half*)s2, (const u32*)wf + 18432, b2);

    outconv_kernel<<<dim3(4, N_BOX), 256, OC_SMEM_BYTES>>>(
        (const __half*)p2, ow, ob, cls, out);
}

// round 16
// speedup vs baseline: 5.3798x; 1.0460x over previous
#include <cuda_runtime.h>
#include <cuda_fp16.h>
#include <cstddef>
#include <cstdint>

typedef unsigned long long u64;
typedef unsigned int u32;

#define N_BOX 1024
#define HF 192
#define CF 64
#define S 32
#define CH 64
#define OUTW 30

// =================== static scratch ===================
// g_s2: conv1 out, [box][34 rows][32 px][64 ch] fp16, rows 0/33 zero guards
__device__ __half g_s2[(size_t)N_BOX * 34 * 32 * 64];
__device__ __half g_buf2[(size_t)N_BOX * S * S * CH];   // conv2 out fp16
// B fragments (single fp16 weights) in mma.sync register order:
// [layer][tap][kstep][ntile][lane] x {b0,b1} u32
__device__ u32 g_wfrag[2 * 9 * 4 * 8 * 32 * 2];

__device__ __forceinline__ u32 ph2(float a, float b) {
    __half2 t = __floats2half2_rn(a, b);
    return *(u32*)&t;
}
__device__ __forceinline__ void mma16816(float* c, const u32* a, u32 b0, u32 b1) {
    asm volatile(
        "mma.sync.aligned.m16n8k16.row.col.f32.f16.f16.f32 "
        "{%0,%1,%2,%3}, {%4,%5,%6,%7}, {%8,%9}, {%0,%1,%2,%3};"
        : "+f"(c[0]), "+f"(c[1]), "+f"(c[2]), "+f"(c[3])
        : "r"(a[0]), "r"(a[1]), "r"(a[2]), "r"(a[3]), "r"(b0), "r"(b1));
}
__device__ __forceinline__ void cp16(u32 dst, const void* src) {
    asm volatile("cp.async.cg.shared.global [%0], [%1], 16;" :: "r"(dst), "l"(src));
}

// ============================================================
// Kernel B: weight prep -> mma B-fragment order, single fp16
// ============================================================
__global__ __launch_bounds__(256) void wprep_kernel(
    const float* __restrict__ w1, const float* __restrict__ w2)
{
    int i = blockIdx.x * 256 + threadIdx.x;
    if (i >= 18432) return;                  // 2 layers * 9 * 4 * 8 * 32
    int layer = i / 9216;
    int r     = i % 9216;
    int tap   = r / 1024;
    int r2    = r & 1023;
    int ks    = (r2 >> 8) & 3;
    int nt    = (r2 >> 5) & 7;
    int lane  = r2 & 31;
    int gid = lane >> 2, ctg = lane & 3;
    int ci0 = ks * 16 + ctg * 2;
    int co  = nt * 8 + gid;
    const float* W = layer ? w2 : w1;

    g_wfrag[i * 2]     = ph2(W[(tap * 64 + ci0) * 64 + co],
                             W[(tap * 64 + ci0 + 1) * 64 + co]);
    g_wfrag[i * 2 + 1] = ph2(W[(tap * 64 + ci0 + 8) * 64 + co],
                             W[(tap * 64 + ci0 + 9) * 64 + co]);
}

// ============================================================
// Kernel C: conv1 with FUSED crop_and_resize, single-pass fp16.
// CTA = one box, 256 threads (8 warps), 2 CTAs/SM.
// ============================================================
#define SPLIT_BYTES 26112
#define SLAB_WORDS  6528
#define C1_OFF_BIAS 52224
#define C1_SMEM_BYTES (52224 + 256)

__global__ __launch_bounds__(256, 2) void conv1_kernel(
    const float* __restrict__ feat,
    const float* __restrict__ boxes,
    const int*   __restrict__ box_ids,
    const u32*   __restrict__ wfrag,
    const float* __restrict__ bias)
{
    extern __shared__ char smraw[];
    float* bias_s = (float*)(smraw + C1_OFF_BIAS);

    int n   = blockIdx.x;
    int t   = threadIdx.x;
    int wid = t >> 5;
    int lane = t & 31;
    int gid = lane >> 2, ctg = lane & 3;

    if (t < 64) bias_s[t] = bias[t];

    // ---- zero this box's guard rows of g_s2 (rows 0 and 33)
    {
        uint4 z4 = make_uint4(0, 0, 0, 0);
        uint4* r0 = (uint4*)&g_s2[((size_t)n * 34 + 0) * 2048];
        uint4* r1 = (uint4*)&g_s2[((size_t)n * 34 + 33) * 2048];
        for (int i = t; i < 256; i += 256) { r0[i] = z4; r1[i] = z4; }
    }

    // box params
    float y1 = boxes[n * 4 + 0], x1 = boxes[n * 4 + 1];
    float y2 = boxes[n * 4 + 2], x2 = boxes[n * 4 + 3];
    int b = box_ids[n];
    const float4* f4 = (const float4*)(feat + (size_t)b * HF * HF * CF);

    // ---- zero x-guards (px_s = 0, 33) once, both buffers
    for (int idx = t; idx < 2 * 96; idx += 256) {
        int c    = idx & 7;
        int side = (idx >> 3) & 1;
        int r    = (idx >> 4) % 6;
        int sb   = idx / 96;
        int pxs  = side ? 33 : 0;
        int sw   = (pxs & 7) << 2;
        int w    = (r * 34 + pxs) * 32 + ((c * 4) ^ sw);
        u32* dst = (u32*)(smraw + sb * SPLIT_BYTES);
        *(uint4*)(dst + w) = make_uint4(0, 0, 0, 0);
    }

    const uint2* wf2 = (const uint2*)wfrag;

    // crop-thread mapping: px = t>>3 (0..31), cg = t&7 (2 chunks of 4 ch)
    int cpx = t >> 3;
    int cg  = t & 7;
    float xs  = (x1 + (float)cpx * (1.f / 31.f) * (x2 - x1)) * (float)(HF - 1);
    float x0f = fminf(fmaxf(floorf(xs), 0.f), (float)(HF - 1));
    float wx  = xs - x0f;
    int x0i = (int)x0f;
    int x1i = min(x0i + 1, HF - 1);
    int csw = ((cpx + 1) & 7) << 2;

    // MMA tile mapping
    int m_lo = wid * 16 + gid;
    int m_hi = m_lo + 8;
    int row_lo = m_lo >> 5, x_lo = m_lo & 31;
    int row_hi = m_hi >> 5, x_hi = m_hi & 31;

#pragma unroll 1
    for (int it = 0; it < 8; it++) {
        // ---- fused crop: fill stage `it` slab (buffer it&1), fp16 single
        {
            u32* shi = (u32*)(smraw + (it & 1) * SPLIT_BYTES);
#pragma unroll
            for (int r = 0; r < 6; r++) {
                int j  = it * 4 + r;                      // 0..33
                float wz = (j == 0 || j == 33) ? 0.f : 1.f;
                int y  = min(max(j - 1, 0), S - 1);
                float ys  = (y1 + (float)y * (1.f / 31.f) * (y2 - y1)) * (float)(HF - 1);
                float y0f = fminf(fmaxf(floorf(ys), 0.f), (float)(HF - 1));
                float wy  = ys - y0f;
                int y0i = (int)y0f;
                int y1i = min(y0i + 1, HF - 1);
                const float4* r0 = f4 + (size_t)y0i * HF * 16;
                const float4* r1 = f4 + (size_t)y1i * HF * 16;
                int base = (r * 34 + cpx + 1) * 32;
                float omx = 1.f - wx, omy = 1.f - wy;
#pragma unroll
                for (int q = 0; q < 2; q++) {
                    int ck = cg * 2 + q;                  // 4-channel chunk
                    float4 v00 = r0[x0i * 16 + ck];
                    float4 v01 = r0[x1i * 16 + ck];
                    float4 v10 = r1[x0i * 16 + ck];
                    float4 v11 = r1[x1i * 16 + ck];
                    float o0 = ((v00.x * omx + v01.x * wx) * omy + (v10.x * omx + v11.x * wx) * wy) * wz;
                    float o1 = ((v00.y * omx + v01.y * wx) * omy + (v10.y * omx + v11.y * wx) * wy) * wz;
                    float o2 = ((v00.z * omx + v01.z * wx) * omy + (v10.z * omx + v11.z * wx) * wy) * wz;
                    float o3 = ((v00.w * omx + v01.w * wx) * omy + (v10.w * omx + v11.w * wx) * wy) * wz;
                    int w = base + ((ck * 2) ^ csw);
                    uint2 Hh;
                    Hh.x = ph2(o0, o1);
                    Hh.y = ph2(o2, o3);
                    *(uint2*)(shi + w) = Hh;
                }
            }
        }
        __syncthreads();   // slab `it` complete; prev iter's other buffer free

        u32* slab = (u32*)(smraw + (it & 1) * SPLIT_BYTES);

        float acc[8][4];
#pragma unroll
        for (int nt = 0; nt < 8; nt++)
#pragma unroll
            for (int j = 0; j < 4; j++) acc[nt][j] = 0.f;

#pragma unroll 1
        for (int tap = 0; tap < 9; tap++) {
            int ky = tap / 3, kx = tap - ky * 3;
            int rl = row_lo + ky, pl = x_lo + kx;
            int rh = row_hi + ky, ph = x_hi + kx;
            int bl_ = (rl * 34 + pl) * 32, sl_ = (pl & 7) << 2;
            int bh_ = (rh * 34 + ph) * 32, sh_ = (ph & 7) << 2;
#pragma unroll
            for (int ks = 0; ks < 4; ks++) {
                int c0 = ks * 8 + ctg, c1 = ks * 8 + 4 + ctg;
                u32 a[4];
                a[0] = slab[bl_ + (c0 ^ sl_)];
                a[1] = slab[bh_ + (c0 ^ sh_)];
                a[2] = slab[bl_ + (c1 ^ sl_)];
                a[3] = slab[bh_ + (c1 ^ sh_)];

                const uint2* wh = wf2 + ((tap * 4 + ks) * 8) * 32 + lane;
#pragma unroll
                for (int nt = 0; nt < 8; nt++) {
                    uint2 bw = __ldg(wh + nt * 32);
                    mma16816(acc[nt], a, bw.x, bw.y);
                }
            }
        }

        // ---- epilogue: bias + ReLU, single-fp16 write to g_s2 (rows +1)
        int y0 = it * 4 + row_lo;
        int y1r = it * 4 + row_hi;
#pragma unroll
        for (int nt = 0; nt < 8; nt++) {
            int co = nt * 8 + ctg * 2;
            float v00 = fmaxf(acc[nt][0] + bias_s[co], 0.f);
            float v01 = fmaxf(acc[nt][1] + bias_s[co + 1], 0.f);
            float v10 = fmaxf(acc[nt][2] + bias_s[co], 0.f);
            float v11 = fmaxf(acc[nt][3] + bias_s[co + 1], 0.f);
            size_t a0 = (((size_t)n * 34 + y0 + 1) * 32 + x_lo) * 64 + co;
            size_t a1 = (((size_t)n * 34 + y1r + 1) * 32 + x_hi) * 64 + co;
            *(u32*)&g_s2[a0] = ph2(v00, v01);
            *(u32*)&g_s2[a1] = ph2(v10, v11);
        }
        // no second sync: double buffer, next crop targets the other buffer
    }
}

// ============================================================
// Kernel D: conv2, single-pass fp16 HMMA.
// cp.async double-buffered slab. 2 CTAs/SM.
// ============================================================
#define C2_OFF_BIAS 52224
#define C2_SMEM_BYTES (52224 + 256)

__global__ __launch_bounds__(256, 2) void conv2_kernel(
    const __half* __restrict__ in,        // g_s2
    const u32*    __restrict__ wfrag,     // layer-1 fragment array
    const float*  __restrict__ bias)
{
    extern __shared__ char smraw[];
    float* bias_s = (float*)(smraw + C2_OFF_BIAS);
    u32 smem_base = (u32)__cvta_generic_to_shared(smraw);

    int n   = blockIdx.x;
    int t   = threadIdx.x;
    int wid = t >> 5;
    int lane = t & 31;
    int gid = lane >> 2, ctg = lane & 3;

    if (t < 64) bias_s[t] = bias[t];

    // zero x-guards for both buffers
    for (int idx = t; idx < 2 * 96; idx += 256) {
        int c    = idx & 7;
        int side = (idx >> 3) & 1;
        int r    = (idx >> 4) % 6;
        int sb   = idx / 96;
        int pxs  = side ? 33 : 0;
        int sw   = (pxs & 7) << 2;
        int w    = (r * 34 + pxs) * 32 + ((c * 4) ^ sw);
        u32* dst = (u32*)(smraw + sb * SPLIT_BYTES);
        *(uint4*)(dst + w) = make_uint4(0, 0, 0, 0);
    }

    const uint2* wf2 = (const uint2*)wfrag;

    int m_lo = wid * 16 + gid;
    int m_hi = m_lo + 8;
    int row_lo = m_lo >> 5, x_lo = m_lo & 31;
    int row_hi = m_hi >> 5, x_hi = m_hi & 31;

    auto preload = [&](int itx, int sel) {
        const uint4* src = (const uint4*)in;
        u32 dbase = smem_base + (u32)sel * SPLIT_BYTES;
#pragma unroll
        for (int idx = t; idx < 1536; idx += 256) {
            int c  = idx & 7;
            int px = (idx >> 3) & 31;
            int r  = idx >> 8;
            const uint4* g = src + ((size_t)(n * 34 + itx * 4 + r) * 32 + px) * 8 + c;
            int sw = ((px + 1) & 7) << 2;
            int w  = (r * 34 + px + 1) * 32 + ((c * 4) ^ sw);
            cp16(dbase + (u32)w * 4, g);
        }
    };

    preload(0, 0);
    asm volatile("cp.async.commit_group;" ::: "memory");

#pragma unroll 1
    for (int it = 0; it < 8; it++) {
        if (it < 7) {
            preload(it + 1, (it + 1) & 1);
            asm volatile("cp.async.commit_group;" ::: "memory");
            asm volatile("cp.async.wait_group 1;" ::: "memory");
        } else {
            asm volatile("cp.async.wait_group 0;" ::: "memory");
        }
        __syncthreads();

        u32* slab = (u32*)(smraw + (it & 1) * SPLIT_BYTES);

        float acc[8][4];
#pragma unroll
        for (int nt = 0; nt < 8; nt++)
#pragma unroll
            for (int j = 0; j < 4; j++) acc[nt][j] = 0.f;

#pragma unroll 1
        for (int tap = 0; tap < 9; tap++) {
            int ky = tap / 3, kx = tap - ky * 3;
            int rl = row_lo + ky, pl = x_lo + kx;
            int rh = row_hi + ky, ph = x_hi + kx;
            int bl_ = (rl * 34 + pl) * 32, sl_ = (pl & 7) << 2;
            int bh_ = (rh * 34 + ph) * 32, sh_ = (ph & 7) << 2;
#pragma unroll
            for (int ks = 0; ks < 4; ks++) {
                int c0 = ks * 8 + ctg, c1 = ks * 8 + 4 + ctg;
                u32 a[4];
                a[0] = slab[bl_ + (c0 ^ sl_)];
                a[1] = slab[bh_ + (c0 ^ sh_)];
                a[2] = slab[bl_ + (c1 ^ sl_)];
                a[3] = slab[bh_ + (c1 ^ sh_)];

                const uint2* wh = wf2 + ((tap * 4 + ks) * 8) * 32 + lane;
#pragma unroll
                for (int nt = 0; nt < 8; nt++) {
                    uint2 bw = __ldg(wh + nt * 32);
                    mma16816(acc[nt], a, bw.x, bw.y);
                }
            }
        }

        int y0 = it * 4 + row_lo;
        int y1r = it * 4 + row_hi;
#pragma unroll
        for (int nt = 0; nt < 8; nt++) {
            int co = nt * 8 + ctg * 2;
            float v00 = fmaxf(acc[nt][0] + bias_s[co], 0.f);
            float v01 = fmaxf(acc[nt][1] + bias_s[co + 1], 0.f);
            float v10 = fmaxf(acc[nt][2] + bias_s[co], 0.f);
            float v11 = fmaxf(acc[nt][3] + bias_s[co + 1], 0.f);
            size_t a0 = (((size_t)n * 32 + y0) * 32 + x_lo) * 64 + co;
            size_t a1 = (((size_t)n * 32 + y1r) * 32 + x_hi) * 64 + co;
            *(u32*)&g_buf2[a0] = ph2(v00, v01);
            *(u32*)&g_buf2[a1] = ph2(v10, v11);
        }
        __syncthreads();
    }
}

// ============================================================
// Kernel E: 3x3 VALID conv, selected class only.
// grid (4, N_BOX): block computes 8 output rows (last block 6),
// one output per thread; input smem channel-contiguous [ry][px][ci]
// with px-pitch 68 floats -> all loads are conflict-free LDS.128.
// ============================================================
#define OC_PXS   68                                   // floats per px slot
#define OC_RYS   (32 * OC_PXS)                        // 2176 floats per row
#define OC_WS_OFF (10 * OC_RYS * 4)                   // 87040
#define OC_SMEM_BYTES (OC_WS_OFF + 2304 + 64)

__global__ __launch_bounds__(256, 2) void outconv_kernel(
    const __half* __restrict__ buf2,
    const float* __restrict__ ow,    // [3][3][64][3]
    const float* __restrict__ ob,
    const int*   __restrict__ cls,
    float*       __restrict__ out)   // [N][30][30]
{
    extern __shared__ char ocsm[];
    float* insm = (float*)ocsm;                  // [ry][px][ci] pitch 68
    float* ws   = (float*)(ocsm + OC_WS_OFF);    // [9][64]

    int n    = blockIdx.y;
    int bx   = blockIdx.x;
    int oy0  = bx * 8;
    int nrow = (bx == 3) ? 6 : 8;                // output rows this block
    int nin  = nrow + 2;                         // input rows staged
    int t    = threadIdx.x;
    int k    = __ldg(&cls[n]);

    for (int i = t; i < 576; i += 256) ws[i] = ow[i * 3 + k];
    float bias = __ldg(&ob[k]);

    // stage input rows oy0..oy0+nin-1, fp16 -> fp32, channel-contiguous
    const uint4* b2 = (const uint4*)buf2;
    for (int idx = t; idx < nin * 32 * 8; idx += 256) {
        int c  = idx & 7;                        // 8-channel chunk
        int px = (idx >> 3) & 31;
        int ry = idx >> 8;
        uint4 v = b2[((size_t)(n * S + oy0 + ry) * S + px) * 8 + c];
        const __half2* hp = (const __half2*)&v;
        float2 f0 = __half22float2(hp[0]);
        float2 f1 = __half22float2(hp[1]);
        float2 f2 = __half22float2(hp[2]);
        float2 f3 = __half22float2(hp[3]);
        float* d = insm + ry * OC_RYS + px * OC_PXS + c * 8;
        ((float4*)d)[0] = make_float4(f0.x, f0.y, f1.x, f1.y);
        ((float4*)d)[1] = make_float4(f2.x, f2.y, f3.x, f3.y);
    }
    __syncthreads();

    int p = t;
    if (p < nrow * OUTW) {
        int oyl = p / OUTW;
        int ox  = p - oyl * OUTW;
        float acc = bias;
        const float* base = insm + oyl * OC_RYS + ox * OC_PXS;
#pragma unroll
        for (int tap = 0; tap < 9; tap++) {
            int ky = tap / 3, kx = tap - ky * 3;
            const float4* ip = (const float4*)(base + ky * OC_RYS + kx * OC_PXS);
            const float4* wp = (const float4*)(ws + tap * 64);
#pragma unroll
            for (int c4 = 0; c4 < 16; c4++) {
                float4 a = ip[c4];
                float4 w = wp[c4];
                acc += a.x * w.x + a.y * w.y + a.z * w.z + a.w * w.w;
            }
        }
        out[(size_t)n * (OUTW * OUTW) + (oy0 + oyl) * OUTW + ox] = acc;
    }
}

// ============================================================
// Launch
// ============================================================
extern "C" void kernel_launch(void* const* d_in, const int* in_sizes, int n_in,
                              void* d_out, int out_size)
{
    const float* features = (const float*)d_in[0];
    const float* boxes    = (const float*)d_in[1];
    const int*   box_ids  = (const int*)d_in[2];
    const int*   cls      = (const int*)d_in[3];
    const float* w1       = (const float*)d_in[4];
    const float* b1       = (const float*)d_in[5];
    const float* w2       = (const float*)d_in[6];
    const float* b2       = (const float*)d_in[7];
    const float* ow       = (const float*)d_in[8];
    const float* ob       = (const float*)d_in[9];
    float* out = (float*)d_out;

    cudaFuncSetAttribute(conv1_kernel,
                         cudaFuncAttributeMaxDynamicSharedMemorySize, C1_SMEM_BYTES);
    cudaFuncSetAttribute(conv2_kernel,
                         cudaFuncAttributeMaxDynamicSharedMemorySize, C2_SMEM_BYTES);
    cudaFuncSetAttribute(outconv_kernel,
                         cudaFuncAttributeMaxDynamicSharedMemorySize, OC_SMEM_BYTES);

    void *s2, *wf, *p2;
    cudaGetSymbolAddress(&s2, g_s2);
    cudaGetSymbolAddress(&wf, g_wfrag);
    cudaGetSymbolAddress(&p2, g_buf2);

    wprep_kernel<<<72, 256>>>(w1, w2);

    conv1_kernel<<<N_BOX, 256, C1_SMEM_BYTES>>>(
        features, boxes, box_ids, (const u32*)wf, b1);
    conv2_kernel<<<N_BOX, 256, C2_SMEM_BYTES>>>(
        (const __half*)s2, (const u32*)wf + 18432, b2);

    outconv_kernel<<<dim3(4, N_BOX), 256, OC_SMEM_BYTES>>>(
        (const __half*)p2, ow, ob, cls, out);
}